// round 8
// baseline (speedup 1.0000x reference)
#include <cuda_runtime.h>
#include <cstdint>

// Problem constants
#define NB   65536
#define SQ   9
#define DM   20
#define NH   4
#define DHD  5
#define DFF  512
#define EPSV 1e-5f

typedef unsigned long long u64;

// 47 MB scratch for y = LN1(attn_out + x)
__device__ __align__(16) float g_y[(size_t)NB * SQ * DM];

// ---------------- f32x2 helpers (Blackwell packed fp32) ----------------
__device__ __forceinline__ u64 fma2(u64 a, u64 b, u64 c) {
    u64 d;
    asm("fma.rn.f32x2 %0, %1, %2, %3;" : "=l"(d) : "l"(a), "l"(b), "l"(c));
    return d;
}
__device__ __forceinline__ u64 mul2(u64 a, u64 b) {
    u64 d;
    asm("mul.rn.f32x2 %0, %1, %2;" : "=l"(d) : "l"(a), "l"(b));
    return d;
}
__device__ __forceinline__ float2 unpack2(u64 a) {
    float2 r;
    asm("mov.b64 {%0, %1}, %2;" : "=f"(r.x), "=f"(r.y) : "l"(a));
    return r;
}
__device__ __forceinline__ u64 pack2(float lo, float hi) {
    u64 d;
    asm("mov.b64 %0, {%1, %2};" : "=l"(d)
        : "r"(__float_as_uint(lo)), "r"(__float_as_uint(hi)));
    return d;
}

// ======================================================================
// Kernel 1: QKV + attention + quirky merge + Wo + residual + LN1 -> g_y
// 32 batches per block, 1 thread per (batch, s) row. 288 threads = 9 warps
// (no partial warp). Dynamic shared memory (76 KB).
// ======================================================================
#define GB 32
#define T1 (GB * SQ)  // 288

// dynamic smem layout (floats):
//   [0,400)        sWq
//   [400,800)      sWk
//   [800,1200)     sWv
//   [1200,1600)    sWo
//   [1600,1720)    sb[6][20]
//   [1720..]       pad to 1728 for 16B alignment
//   [1728, +5760)  sK [GB][SQ][DM]
//   [7488, +5760)  sV
//   [13248,+5760)  sM [GB][SQ*DM]
#define A_WQ 0
#define A_WK 400
#define A_WV 800
#define A_WO 1200
#define A_SB 1600
#define A_SK 1728
#define A_SV (A_SK + GB*SQ*DM)
#define A_SM (A_SV + GB*SQ*DM)
#define SMEM1 ((A_SM + GB*SQ*DM) * 4)

__global__ void __launch_bounds__(T1) k_attn(
    const float* __restrict__ X,
    const float* __restrict__ Wq, const float* __restrict__ bq,
    const float* __restrict__ Wk, const float* __restrict__ bk,
    const float* __restrict__ Wv, const float* __restrict__ bv,
    const float* __restrict__ Wo, const float* __restrict__ bo,
    const float* __restrict__ g1, const float* __restrict__ b1)
{
    extern __shared__ __align__(16) float dsm[];
    float* sWq = dsm + A_WQ;
    float* sWk = dsm + A_WK;
    float* sWv = dsm + A_WV;
    float* sWo = dsm + A_WO;
    float* sb  = dsm + A_SB;   // 6 x 20
    float* sK  = dsm + A_SK;   // [GB][SQ][DM]
    float* sV  = dsm + A_SV;
    float* sM  = dsm + A_SM;   // [GB][SQ*DM]

    const int tid = threadIdx.x;
    for (int i = tid; i < DM * DM; i += T1) {
        sWq[i] = Wq[i]; sWk[i] = Wk[i]; sWv[i] = Wv[i]; sWo[i] = Wo[i];
    }
    if (tid < DM) {
        sb[0*DM+tid] = bq[tid]; sb[1*DM+tid] = bk[tid]; sb[2*DM+tid] = bv[tid];
        sb[3*DM+tid] = bo[tid]; sb[4*DM+tid] = g1[tid]; sb[5*DM+tid] = b1[tid];
    }

    const int bl = tid / SQ;
    const int s  = tid - bl * SQ;
    const size_t row = (size_t)(blockIdx.x * GB + bl) * SQ + s;

    // Load x row (20 floats, 16B aligned since 80 % 16 == 0)
    float x[DM];
    {
        const float4* xr = (const float4*)(X + row * DM);
        #pragma unroll
        for (int i = 0; i < 5; i++) {
            float4 t = xr[i];
            x[4*i] = t.x; x[4*i+1] = t.y; x[4*i+2] = t.z; x[4*i+3] = t.w;
        }
    }
    __syncthreads();

    // q, k, v rows — packed f32x2 accumulators over output-dim pairs
    u64 q2[10], k2[10], v2[10];
    {
        const u64* bq2 = (const u64*)(sb + 0*DM);
        const u64* bk2 = (const u64*)(sb + 1*DM);
        const u64* bv2 = (const u64*)(sb + 2*DM);
        #pragma unroll
        for (int p = 0; p < 10; p++) { q2[p] = bq2[p]; k2[p] = bk2[p]; v2[p] = bv2[p]; }
    }
    #pragma unroll
    for (int kd = 0; kd < DM; kd++) {
        const u64 x2 = pack2(x[kd], x[kd]);
        const ulonglong2* wq = (const ulonglong2*)(sWq + kd * DM);
        const ulonglong2* wk = (const ulonglong2*)(sWk + kd * DM);
        const ulonglong2* wv = (const ulonglong2*)(sWv + kd * DM);
        #pragma unroll
        for (int p = 0; p < 5; p++) {
            const ulonglong2 a = wq[p];
            q2[2*p]   = fma2(x2, a.x, q2[2*p]);
            q2[2*p+1] = fma2(x2, a.y, q2[2*p+1]);
            const ulonglong2 b = wk[p];
            k2[2*p]   = fma2(x2, b.x, k2[2*p]);
            k2[2*p+1] = fma2(x2, b.y, k2[2*p+1]);
            const ulonglong2 c = wv[p];
            v2[2*p]   = fma2(x2, c.x, v2[2*p]);
            v2[2*p+1] = fma2(x2, c.y, v2[2*p+1]);
        }
    }
    // store k, v rows to smem (pair layout == float layout)
    {
        u64* kp = (u64*)(sK + (bl * SQ + s) * DM);
        u64* vp = (u64*)(sV + (bl * SQ + s) * DM);
        #pragma unroll
        for (int p = 0; p < 10; p++) { kp[p] = k2[p]; vp[p] = v2[p]; }
    }
    float q[DM];
    #pragma unroll
    for (int p = 0; p < 10; p++) {
        float2 t = unpack2(q2[p]);
        q[2*p] = t.x; q[2*p+1] = t.y;
    }
    __syncthreads();

    // Attention per head for this query row; write into merged buffer with
    // the reference's transpose(0,1,3,2).reshape quirk:
    //   flat f = h*45 + dh*9 + s  ->  merged[f/20][f%20]
    #pragma unroll
    for (int h = 0; h < NH; h++) {
        float sc[SQ];
        float mx = -1e30f;
        #pragma unroll
        for (int j = 0; j < SQ; j++) {
            const float* kr = sK + (bl * SQ + j) * DM + h * DHD;
            float a = 0.f;
            #pragma unroll
            for (int dh = 0; dh < DHD; dh++)
                a = fmaf(q[h * DHD + dh], kr[dh], a);
            a *= (1.0f / 3.0f);
            sc[j] = a;
            mx = fmaxf(mx, a);
        }
        float den = 0.f;
        #pragma unroll
        for (int j = 0; j < SQ; j++) { sc[j] = __expf(sc[j] - mx); den += sc[j]; }
        const float inv = 1.0f / den;
        float ctx[DHD] = {0.f, 0.f, 0.f, 0.f, 0.f};
        #pragma unroll
        for (int j = 0; j < SQ; j++) {
            const float p = sc[j];
            const float* vr = sV + (bl * SQ + j) * DM + h * DHD;
            #pragma unroll
            for (int dh = 0; dh < DHD; dh++)
                ctx[dh] = fmaf(p, vr[dh], ctx[dh]);
        }
        #pragma unroll
        for (int dh = 0; dh < DHD; dh++)
            sM[bl * (SQ*DM) + h * 45 + dh * 9 + s] = ctx[dh] * inv;
    }
    __syncthreads();

    // attn_out = merged_row @ Wo + bo (packed) ; residual ; LN1
    u64 ao2[10];
    {
        const u64* bo2 = (const u64*)(sb + 3*DM);
        #pragma unroll
        for (int p = 0; p < 10; p++) ao2[p] = bo2[p];
    }
    #pragma unroll
    for (int kd = 0; kd < DM; kd++) {
        const float m = sM[bl * (SQ*DM) + s * DM + kd];
        const u64 m2 = pack2(m, m);
        const ulonglong2* wo = (const ulonglong2*)(sWo + kd * DM);
        #pragma unroll
        for (int p = 0; p < 5; p++) {
            const ulonglong2 w = wo[p];
            ao2[2*p]   = fma2(m2, w.x, ao2[2*p]);
            ao2[2*p+1] = fma2(m2, w.y, ao2[2*p+1]);
        }
    }
    float r[DM];
    float mean = 0.f;
    #pragma unroll
    for (int p = 0; p < 10; p++) {
        float2 a = unpack2(ao2[p]);
        r[2*p]   = a.x + x[2*p];
        r[2*p+1] = a.y + x[2*p+1];
        mean += r[2*p] + r[2*p+1];
    }
    mean *= (1.0f / 20.0f);
    float var = 0.f;
    #pragma unroll
    for (int d = 0; d < DM; d++) { const float t = r[d] - mean; var = fmaf(t, t, var); }
    var *= (1.0f / 20.0f);
    const float rstd = rsqrtf(var + EPSV);

    const float* sg1 = sb + 4*DM;
    const float* sb1 = sb + 5*DM;
    float4* yo = (float4*)(g_y + row * DM);
    #pragma unroll
    for (int i = 0; i < 5; i++) {
        float4 t;
        t.x = (r[4*i+0] - mean) * rstd * sg1[4*i+0] + sb1[4*i+0];
        t.y = (r[4*i+1] - mean) * rstd * sg1[4*i+1] + sb1[4*i+1];
        t.z = (r[4*i+2] - mean) * rstd * sg1[4*i+2] + sb1[4*i+2];
        t.w = (r[4*i+3] - mean) * rstd * sg1[4*i+3] + sb1[4*i+3];
        yo[i] = t;
    }
}

// ======================================================================
// Kernel 2: FFN (relu(y@W1)@W2) + residual + LN2 -> out
// 256 threads, 2 rows/thread, 512 rows/block. f32x2 packed FMA.
// Software-pipelined: up-proj chains for the NEXT j-pair are started
// (and their LDS issued) before the down-projection of the current pair,
// so weight-load latency and the relu junction hide under fma work.
// Dynamic shared: W1^T [512][20] + W2 [512][20] + g2 + b2 = 82,080 B
// ======================================================================
#define T2 256
#define RPB 512
#define SMEM2 ((DFF * DM * 2 + 2 * DM) * 4)

__device__ __forceinline__ void ln2_store(const u64* yp, const u64* op,
                                          const float* sg2, const float* sb2,
                                          float* outrow)
{
    float r[DM];
    float mean = 0.f;
    #pragma unroll
    for (int p = 0; p < 10; p++) {
        float2 yv = unpack2(yp[p]);
        float2 fv = unpack2(op[p]);
        r[2*p]   = yv.x + fv.x;
        r[2*p+1] = yv.y + fv.y;
        mean += r[2*p] + r[2*p+1];
    }
    mean *= (1.0f / 20.0f);
    float var = 0.f;
    #pragma unroll
    for (int d = 0; d < DM; d++) { const float t = r[d] - mean; var = fmaf(t, t, var); }
    var *= (1.0f / 20.0f);
    const float rstd = rsqrtf(var + EPSV);
    float4* o4 = (float4*)outrow;
    #pragma unroll
    for (int i = 0; i < 5; i++) {
        float4 t;
        t.x = (r[4*i+0] - mean) * rstd * sg2[4*i+0] + sb2[4*i+0];
        t.y = (r[4*i+1] - mean) * rstd * sg2[4*i+1] + sb2[4*i+1];
        t.z = (r[4*i+2] - mean) * rstd * sg2[4*i+2] + sb2[4*i+2];
        t.w = (r[4*i+3] - mean) * rstd * sg2[4*i+3] + sb2[4*i+3];
        o4[i] = t;
    }
}

// Start the 4 up-projection chains (rows a,b x hidden units j,j+1) for the
// j-pair whose W1^T rows begin at w1p. 10 LDS.128 + 40 fma2, 4 independent
// chains. Chains are NOT finalized here.
__device__ __forceinline__ void chains2(const u64* ya, const u64* yb,
                                        const ulonglong2* w1p,
                                        u64& c0, u64& c1, u64& c2, u64& c3)
{
    ulonglong2 w;
    w = w1p[0];
    c0 = mul2(ya[0], w.x);           c1 = mul2(yb[0], w.x);
    c0 = fma2(ya[1], w.y, c0);       c1 = fma2(yb[1], w.y, c1);
    w = w1p[5];
    c2 = mul2(ya[0], w.x);           c3 = mul2(yb[0], w.x);
    c2 = fma2(ya[1], w.y, c2);       c3 = fma2(yb[1], w.y, c3);
    w = w1p[1];
    c0 = fma2(ya[2], w.x, c0);       c1 = fma2(yb[2], w.x, c1);
    c0 = fma2(ya[3], w.y, c0);       c1 = fma2(yb[3], w.y, c1);
    w = w1p[6];
    c2 = fma2(ya[2], w.x, c2);       c3 = fma2(yb[2], w.x, c3);
    c2 = fma2(ya[3], w.y, c2);       c3 = fma2(yb[3], w.y, c3);
    w = w1p[2];
    c0 = fma2(ya[4], w.x, c0);       c1 = fma2(yb[4], w.x, c1);
    c0 = fma2(ya[5], w.y, c0);       c1 = fma2(yb[5], w.y, c1);
    w = w1p[7];
    c2 = fma2(ya[4], w.x, c2);       c3 = fma2(yb[4], w.x, c3);
    c2 = fma2(ya[5], w.y, c2);       c3 = fma2(yb[5], w.y, c3);
    w = w1p[3];
    c0 = fma2(ya[6], w.x, c0);       c1 = fma2(yb[6], w.x, c1);
    c0 = fma2(ya[7], w.y, c0);       c1 = fma2(yb[7], w.y, c1);
    w = w1p[8];
    c2 = fma2(ya[6], w.x, c2);       c3 = fma2(yb[6], w.x, c3);
    c2 = fma2(ya[7], w.y, c2);       c3 = fma2(yb[7], w.y, c3);
    w = w1p[4];
    c0 = fma2(ya[8], w.x, c0);       c1 = fma2(yb[8], w.x, c1);
    c0 = fma2(ya[9], w.y, c0);       c1 = fma2(yb[9], w.y, c1);
    w = w1p[9];
    c2 = fma2(ya[8], w.x, c2);       c3 = fma2(yb[8], w.x, c3);
    c2 = fma2(ya[9], w.y, c2);       c3 = fma2(yb[9], w.y, c3);
}

__device__ __forceinline__ float hrelu(u64 c) {
    float2 f = unpack2(c);
    return fmaxf(f.x + f.y, 0.f);
}

__global__ void __launch_bounds__(T2, 2) k_ffn(
    const float* __restrict__ W1, const float* __restrict__ W2,
    const float* __restrict__ g2, const float* __restrict__ b2,
    float* __restrict__ Out)
{
    extern __shared__ __align__(16) float sm[];
    float* sW1t = sm;                 // [512][20], transposed: row j = W1[:, j]
    float* sW2  = sm + DFF * DM;      // [512][20], as stored
    float* sg2  = sm + 2 * DFF * DM;
    float* sb2  = sg2 + DM;

    const int tid = threadIdx.x;
    for (int i = tid; i < DFF * DM; i += T2) {
        const int k = i / DFF;        // W1 is [20][512] row-major
        const int j = i - k * DFF;
        sW1t[j * DM + k] = W1[i];
        sW2[i] = W2[i];               // W2 is [512][20] row-major, direct copy
    }
    if (tid < DM) { sg2[tid] = g2[tid]; sb2[tid] = b2[tid]; }
    __syncthreads();

    const size_t r0 = (size_t)blockIdx.x * RPB + (size_t)tid * 2;

    // Load two y rows as packed f32x2 pairs (rows are 80B, 16B aligned)
    u64 ya[10], yb[10];
    {
        const ulonglong2* y0 = (const ulonglong2*)(g_y + r0 * DM);
        const ulonglong2* y1 = (const ulonglong2*)(g_y + (r0 + 1) * DM);
        #pragma unroll
        for (int p = 0; p < 5; p++) {
            ulonglong2 a = y0[p]; ya[2*p] = a.x; ya[2*p+1] = a.y;
            ulonglong2 b = y1[p]; yb[2*p] = b.x; yb[2*p+1] = b.y;
        }
    }

    u64 oa[10], ob[10];
    #pragma unroll
    for (int p = 0; p < 10; p++) { oa[p] = 0ULL; ob[p] = 0ULL; }

    const ulonglong2* w1base = (const ulonglong2*)sW1t;
    const ulonglong2* w2base = (const ulonglong2*)sW2;

    // Prologue: start chains for pair 0
    u64 c0, c1, c2, c3;
    chains2(ya, yb, w1base, c0, c1, c2, c3);

    #pragma unroll 1
    for (int j = 0; j < DFF - 2; j += 2) {
        // finalize current pair: relu + splat
        const u64 hha = pack2(hrelu(c0), hrelu(c0));
        const u64 hhb = pack2(hrelu(c1), hrelu(c1));
        const u64 hhc = pack2(hrelu(c2), hrelu(c2));
        const u64 hhd = pack2(hrelu(c3), hrelu(c3));

        // start next pair's chains (independent of hh*) — LDS + fma2 here
        // hide under the down-projection below
        chains2(ya, yb, w1base + (j + 2) * 5, c0, c1, c2, c3);

        // down-projection for current pair
        const ulonglong2* q1 = w2base + j * 5;
        #pragma unroll
        for (int p = 0; p < 5; p++) {
            const ulonglong2 wA = q1[p];
            const ulonglong2 wB = q1[p + 5];
            oa[2*p]   = fma2(hha, wA.x, oa[2*p]);
            oa[2*p+1] = fma2(hha, wA.y, oa[2*p+1]);
            ob[2*p]   = fma2(hhb, wA.x, ob[2*p]);
            ob[2*p+1] = fma2(hhb, wA.y, ob[2*p+1]);
            oa[2*p]   = fma2(hhc, wB.x, oa[2*p]);
            oa[2*p+1] = fma2(hhc, wB.y, oa[2*p+1]);
            ob[2*p]   = fma2(hhd, wB.x, ob[2*p]);
            ob[2*p+1] = fma2(hhd, wB.y, ob[2*p+1]);
        }
    }

    // Epilogue: last pair (j = DFF-2)
    {
        const u64 hha = pack2(hrelu(c0), hrelu(c0));
        const u64 hhb = pack2(hrelu(c1), hrelu(c1));
        const u64 hhc = pack2(hrelu(c2), hrelu(c2));
        const u64 hhd = pack2(hrelu(c3), hrelu(c3));
        const ulonglong2* q1 = w2base + (DFF - 2) * 5;
        #pragma unroll
        for (int p = 0; p < 5; p++) {
            const ulonglong2 wA = q1[p];
            const ulonglong2 wB = q1[p + 5];
            oa[2*p]   = fma2(hha, wA.x, oa[2*p]);
            oa[2*p+1] = fma2(hha, wA.y, oa[2*p+1]);
            ob[2*p]   = fma2(hhb, wA.x, ob[2*p]);
            ob[2*p+1] = fma2(hhb, wA.y, ob[2*p+1]);
            oa[2*p]   = fma2(hhc, wB.x, oa[2*p]);
            oa[2*p+1] = fma2(hhc, wB.y, oa[2*p+1]);
            ob[2*p]   = fma2(hhd, wB.x, ob[2*p]);
            ob[2*p+1] = fma2(hhd, wB.y, ob[2*p+1]);
        }
    }

    ln2_store(ya, oa, sg2, sb2, Out + r0 * DM);
    ln2_store(yb, ob, sg2, sb2, Out + (r0 + 1) * DM);
}

// ======================================================================
// Launch
// ======================================================================
extern "C" void kernel_launch(void* const* d_in, const int* in_sizes, int n_in,
                              void* d_out, int out_size)
{
    (void)in_sizes; (void)n_in; (void)out_size;
    const float* X  = (const float*)d_in[0];
    const float* Wq = (const float*)d_in[1];
    const float* bq = (const float*)d_in[2];
    const float* Wk = (const float*)d_in[3];
    const float* bk = (const float*)d_in[4];
    const float* Wv = (const float*)d_in[5];
    const float* bv = (const float*)d_in[6];
    const float* Wo = (const float*)d_in[7];
    const float* bo = (const float*)d_in[8];
    const float* g1 = (const float*)d_in[9];
    const float* b1 = (const float*)d_in[10];
    const float* W1 = (const float*)d_in[11];
    const float* W2 = (const float*)d_in[12];
    const float* g2 = (const float*)d_in[13];
    const float* b2 = (const float*)d_in[14];
    float* Out = (float*)d_out;

    cudaFuncSetAttribute(k_attn, cudaFuncAttributeMaxDynamicSharedMemorySize, SMEM1);
    cudaFuncSetAttribute(k_ffn, cudaFuncAttributeMaxDynamicSharedMemorySize, SMEM2);

    k_attn<<<NB / GB, T1, SMEM1>>>(X, Wq, bq, Wk, bk, Wv, bv, Wo, bo, g1, b1);
    k_ffn<<<(NB * SQ) / RPB, T2, SMEM2>>>(W1, W2, g2, b2, Out);
}

// round 9
// speedup vs baseline: 1.0051x; 1.0051x over previous
#include <cuda_runtime.h>
#include <cstdint>

// Problem constants
#define NB   65536
#define SQ   9
#define DM   20
#define NH   4
#define DHD  5
#define DFF  512
#define EPSV 1e-5f

typedef unsigned long long u64;

// 47 MB scratch for y = LN1(attn_out + x)
__device__ __align__(16) float g_y[(size_t)NB * SQ * DM];

// ---------------- f32x2 helpers (Blackwell packed fp32) ----------------
__device__ __forceinline__ u64 fma2(u64 a, u64 b, u64 c) {
    u64 d;
    asm("fma.rn.f32x2 %0, %1, %2, %3;" : "=l"(d) : "l"(a), "l"(b), "l"(c));
    return d;
}
__device__ __forceinline__ u64 mul2(u64 a, u64 b) {
    u64 d;
    asm("mul.rn.f32x2 %0, %1, %2;" : "=l"(d) : "l"(a), "l"(b));
    return d;
}
__device__ __forceinline__ float2 unpack2(u64 a) {
    float2 r;
    asm("mov.b64 {%0, %1}, %2;" : "=f"(r.x), "=f"(r.y) : "l"(a));
    return r;
}
__device__ __forceinline__ u64 pack2(float lo, float hi) {
    u64 d;
    asm("mov.b64 %0, {%1, %2};" : "=l"(d)
        : "r"(__float_as_uint(lo)), "r"(__float_as_uint(hi)));
    return d;
}

// ======================================================================
// Kernel 1: QKV + attention + quirky merge + Wo + residual + LN1 -> g_y
// 32 batches per block, 1 thread per (batch, s) row. 288 threads = 9 warps
// (no partial warp). Dynamic shared memory (76 KB).
// ======================================================================
#define GB 32
#define T1 (GB * SQ)  // 288

// dynamic smem layout (floats):
//   [0,400)        sWq
//   [400,800)      sWk
//   [800,1200)     sWv
//   [1200,1600)    sWo
//   [1600,1720)    sb[6][20]
//   [1720..]       pad to 1728 for 16B alignment
//   [1728, +5760)  sK [GB][SQ][DM]
//   [7488, +5760)  sV
//   [13248,+5760)  sM [GB][SQ*DM]
#define A_WQ 0
#define A_WK 400
#define A_WV 800
#define A_WO 1200
#define A_SB 1600
#define A_SK 1728
#define A_SV (A_SK + GB*SQ*DM)
#define A_SM (A_SV + GB*SQ*DM)
#define SMEM1 ((A_SM + GB*SQ*DM) * 4)

__global__ void __launch_bounds__(T1) k_attn(
    const float* __restrict__ X,
    const float* __restrict__ Wq, const float* __restrict__ bq,
    const float* __restrict__ Wk, const float* __restrict__ bk,
    const float* __restrict__ Wv, const float* __restrict__ bv,
    const float* __restrict__ Wo, const float* __restrict__ bo,
    const float* __restrict__ g1, const float* __restrict__ b1)
{
    extern __shared__ __align__(16) float dsm[];
    float* sWq = dsm + A_WQ;
    float* sWk = dsm + A_WK;
    float* sWv = dsm + A_WV;
    float* sWo = dsm + A_WO;
    float* sb  = dsm + A_SB;   // 6 x 20
    float* sK  = dsm + A_SK;   // [GB][SQ][DM]
    float* sV  = dsm + A_SV;
    float* sM  = dsm + A_SM;   // [GB][SQ*DM]

    const int tid = threadIdx.x;
    for (int i = tid; i < DM * DM; i += T1) {
        sWq[i] = Wq[i]; sWk[i] = Wk[i]; sWv[i] = Wv[i]; sWo[i] = Wo[i];
    }
    if (tid < DM) {
        sb[0*DM+tid] = bq[tid]; sb[1*DM+tid] = bk[tid]; sb[2*DM+tid] = bv[tid];
        sb[3*DM+tid] = bo[tid]; sb[4*DM+tid] = g1[tid]; sb[5*DM+tid] = b1[tid];
    }

    const int bl = tid / SQ;
    const int s  = tid - bl * SQ;
    const size_t row = (size_t)(blockIdx.x * GB + bl) * SQ + s;

    // Load x row (20 floats, 16B aligned since 80 % 16 == 0)
    float x[DM];
    {
        const float4* xr = (const float4*)(X + row * DM);
        #pragma unroll
        for (int i = 0; i < 5; i++) {
            float4 t = xr[i];
            x[4*i] = t.x; x[4*i+1] = t.y; x[4*i+2] = t.z; x[4*i+3] = t.w;
        }
    }
    __syncthreads();

    // q, k, v rows — packed f32x2 accumulators over output-dim pairs
    u64 q2[10], k2[10], v2[10];
    {
        const u64* bq2 = (const u64*)(sb + 0*DM);
        const u64* bk2 = (const u64*)(sb + 1*DM);
        const u64* bv2 = (const u64*)(sb + 2*DM);
        #pragma unroll
        for (int p = 0; p < 10; p++) { q2[p] = bq2[p]; k2[p] = bk2[p]; v2[p] = bv2[p]; }
    }
    #pragma unroll
    for (int kd = 0; kd < DM; kd++) {
        const u64 x2 = pack2(x[kd], x[kd]);
        const ulonglong2* wq = (const ulonglong2*)(sWq + kd * DM);
        const ulonglong2* wk = (const ulonglong2*)(sWk + kd * DM);
        const ulonglong2* wv = (const ulonglong2*)(sWv + kd * DM);
        #pragma unroll
        for (int p = 0; p < 5; p++) {
            const ulonglong2 a = wq[p];
            q2[2*p]   = fma2(x2, a.x, q2[2*p]);
            q2[2*p+1] = fma2(x2, a.y, q2[2*p+1]);
            const ulonglong2 b = wk[p];
            k2[2*p]   = fma2(x2, b.x, k2[2*p]);
            k2[2*p+1] = fma2(x2, b.y, k2[2*p+1]);
            const ulonglong2 c = wv[p];
            v2[2*p]   = fma2(x2, c.x, v2[2*p]);
            v2[2*p+1] = fma2(x2, c.y, v2[2*p+1]);
        }
    }
    // store k, v rows to smem (pair layout == float layout)
    {
        u64* kp = (u64*)(sK + (bl * SQ + s) * DM);
        u64* vp = (u64*)(sV + (bl * SQ + s) * DM);
        #pragma unroll
        for (int p = 0; p < 10; p++) { kp[p] = k2[p]; vp[p] = v2[p]; }
    }
    float q[DM];
    #pragma unroll
    for (int p = 0; p < 10; p++) {
        float2 t = unpack2(q2[p]);
        q[2*p] = t.x; q[2*p+1] = t.y;
    }
    __syncthreads();

    // Attention per head for this query row; write into merged buffer with
    // the reference's transpose(0,1,3,2).reshape quirk:
    //   flat f = h*45 + dh*9 + s  ->  merged[f/20][f%20]
    #pragma unroll
    for (int h = 0; h < NH; h++) {
        float sc[SQ];
        float mx = -1e30f;
        #pragma unroll
        for (int j = 0; j < SQ; j++) {
            const float* kr = sK + (bl * SQ + j) * DM + h * DHD;
            float a = 0.f;
            #pragma unroll
            for (int dh = 0; dh < DHD; dh++)
                a = fmaf(q[h * DHD + dh], kr[dh], a);
            a *= (1.0f / 3.0f);
            sc[j] = a;
            mx = fmaxf(mx, a);
        }
        float den = 0.f;
        #pragma unroll
        for (int j = 0; j < SQ; j++) { sc[j] = __expf(sc[j] - mx); den += sc[j]; }
        const float inv = 1.0f / den;
        float ctx[DHD] = {0.f, 0.f, 0.f, 0.f, 0.f};
        #pragma unroll
        for (int j = 0; j < SQ; j++) {
            const float p = sc[j];
            const float* vr = sV + (bl * SQ + j) * DM + h * DHD;
            #pragma unroll
            for (int dh = 0; dh < DHD; dh++)
                ctx[dh] = fmaf(p, vr[dh], ctx[dh]);
        }
        #pragma unroll
        for (int dh = 0; dh < DHD; dh++)
            sM[bl * (SQ*DM) + h * 45 + dh * 9 + s] = ctx[dh] * inv;
    }
    __syncthreads();

    // attn_out = merged_row @ Wo + bo (packed) ; residual ; LN1
    u64 ao2[10];
    {
        const u64* bo2 = (const u64*)(sb + 3*DM);
        #pragma unroll
        for (int p = 0; p < 10; p++) ao2[p] = bo2[p];
    }
    #pragma unroll
    for (int kd = 0; kd < DM; kd++) {
        const float m = sM[bl * (SQ*DM) + s * DM + kd];
        const u64 m2 = pack2(m, m);
        const ulonglong2* wo = (const ulonglong2*)(sWo + kd * DM);
        #pragma unroll
        for (int p = 0; p < 5; p++) {
            const ulonglong2 w = wo[p];
            ao2[2*p]   = fma2(m2, w.x, ao2[2*p]);
            ao2[2*p+1] = fma2(m2, w.y, ao2[2*p+1]);
        }
    }
    float r[DM];
    float mean = 0.f;
    #pragma unroll
    for (int p = 0; p < 10; p++) {
        float2 a = unpack2(ao2[p]);
        r[2*p]   = a.x + x[2*p];
        r[2*p+1] = a.y + x[2*p+1];
        mean += r[2*p] + r[2*p+1];
    }
    mean *= (1.0f / 20.0f);
    float var = 0.f;
    #pragma unroll
    for (int d = 0; d < DM; d++) { const float t = r[d] - mean; var = fmaf(t, t, var); }
    var *= (1.0f / 20.0f);
    const float rstd = rsqrtf(var + EPSV);

    const float* sg1 = sb + 4*DM;
    const float* sb1 = sb + 5*DM;
    float4* yo = (float4*)(g_y + row * DM);
    #pragma unroll
    for (int i = 0; i < 5; i++) {
        float4 t;
        t.x = (r[4*i+0] - mean) * rstd * sg1[4*i+0] + sb1[4*i+0];
        t.y = (r[4*i+1] - mean) * rstd * sg1[4*i+1] + sb1[4*i+1];
        t.z = (r[4*i+2] - mean) * rstd * sg1[4*i+2] + sb1[4*i+2];
        t.w = (r[4*i+3] - mean) * rstd * sg1[4*i+3] + sb1[4*i+3];
        yo[i] = t;
    }
}

// ======================================================================
// Kernel 2: FFN (relu(y@W1)@W2) + residual + LN2 -> out
// 256 threads, 2 rows/thread, 512 rows/block. f32x2 packed FMA.
// Software-pipelined: up-proj chains for the NEXT j-pair are started
// (and their LDS issued) before the down-projection of the current pair,
// so weight-load latency and the relu junction hide under fma work.
// Dynamic shared: W1^T [512][20] + W2 [512][20] + g2 + b2 = 82,080 B
// ======================================================================
#define T2 256
#define RPB 512
#define SMEM2 ((DFF * DM * 2 + 2 * DM) * 4)

__device__ __forceinline__ void ln2_store(const u64* yp, const u64* op,
                                          const float* sg2, const float* sb2,
                                          float* outrow)
{
    float r[DM];
    float mean = 0.f;
    #pragma unroll
    for (int p = 0; p < 10; p++) {
        float2 yv = unpack2(yp[p]);
        float2 fv = unpack2(op[p]);
        r[2*p]   = yv.x + fv.x;
        r[2*p+1] = yv.y + fv.y;
        mean += r[2*p] + r[2*p+1];
    }
    mean *= (1.0f / 20.0f);
    float var = 0.f;
    #pragma unroll
    for (int d = 0; d < DM; d++) { const float t = r[d] - mean; var = fmaf(t, t, var); }
    var *= (1.0f / 20.0f);
    const float rstd = rsqrtf(var + EPSV);
    float4* o4 = (float4*)outrow;
    #pragma unroll
    for (int i = 0; i < 5; i++) {
        float4 t;
        t.x = (r[4*i+0] - mean) * rstd * sg2[4*i+0] + sb2[4*i+0];
        t.y = (r[4*i+1] - mean) * rstd * sg2[4*i+1] + sb2[4*i+1];
        t.z = (r[4*i+2] - mean) * rstd * sg2[4*i+2] + sb2[4*i+2];
        t.w = (r[4*i+3] - mean) * rstd * sg2[4*i+3] + sb2[4*i+3];
        o4[i] = t;
    }
}

// Start the 4 up-projection chains (rows a,b x hidden units j,j+1) for the
// j-pair whose W1^T rows begin at w1p. 10 LDS.128 + 40 fma2, 4 independent
// chains. Chains are NOT finalized here.
__device__ __forceinline__ void chains2(const u64* ya, const u64* yb,
                                        const ulonglong2* w1p,
                                        u64& c0, u64& c1, u64& c2, u64& c3)
{
    ulonglong2 w;
    w = w1p[0];
    c0 = mul2(ya[0], w.x);           c1 = mul2(yb[0], w.x);
    c0 = fma2(ya[1], w.y, c0);       c1 = fma2(yb[1], w.y, c1);
    w = w1p[5];
    c2 = mul2(ya[0], w.x);           c3 = mul2(yb[0], w.x);
    c2 = fma2(ya[1], w.y, c2);       c3 = fma2(yb[1], w.y, c3);
    w = w1p[1];
    c0 = fma2(ya[2], w.x, c0);       c1 = fma2(yb[2], w.x, c1);
    c0 = fma2(ya[3], w.y, c0);       c1 = fma2(yb[3], w.y, c1);
    w = w1p[6];
    c2 = fma2(ya[2], w.x, c2);       c3 = fma2(yb[2], w.x, c3);
    c2 = fma2(ya[3], w.y, c2);       c3 = fma2(yb[3], w.y, c3);
    w = w1p[2];
    c0 = fma2(ya[4], w.x, c0);       c1 = fma2(yb[4], w.x, c1);
    c0 = fma2(ya[5], w.y, c0);       c1 = fma2(yb[5], w.y, c1);
    w = w1p[7];
    c2 = fma2(ya[4], w.x, c2);       c3 = fma2(yb[4], w.x, c3);
    c2 = fma2(ya[5], w.y, c2);       c3 = fma2(yb[5], w.y, c3);
    w = w1p[3];
    c0 = fma2(ya[6], w.x, c0);       c1 = fma2(yb[6], w.x, c1);
    c0 = fma2(ya[7], w.y, c0);       c1 = fma2(yb[7], w.y, c1);
    w = w1p[8];
    c2 = fma2(ya[6], w.x, c2);       c3 = fma2(yb[6], w.x, c3);
    c2 = fma2(ya[7], w.y, c2);       c3 = fma2(yb[7], w.y, c3);
    w = w1p[4];
    c0 = fma2(ya[8], w.x, c0);       c1 = fma2(yb[8], w.x, c1);
    c0 = fma2(ya[9], w.y, c0);       c1 = fma2(yb[9], w.y, c1);
    w = w1p[9];
    c2 = fma2(ya[8], w.x, c2);       c3 = fma2(yb[8], w.x, c3);
    c2 = fma2(ya[9], w.y, c2);       c3 = fma2(yb[9], w.y, c3);
}

__device__ __forceinline__ float hrelu(u64 c) {
    float2 f = unpack2(c);
    return fmaxf(f.x + f.y, 0.f);
}

__global__ void __launch_bounds__(T2, 2) k_ffn(
    const float* __restrict__ W1, const float* __restrict__ W2,
    const float* __restrict__ g2, const float* __restrict__ b2,
    float* __restrict__ Out)
{
    extern __shared__ __align__(16) float sm[];
    float* sW1t = sm;                 // [512][20], transposed: row j = W1[:, j]
    float* sW2  = sm + DFF * DM;      // [512][20], as stored
    float* sg2  = sm + 2 * DFF * DM;
    float* sb2  = sg2 + DM;

    const int tid = threadIdx.x;
    for (int i = tid; i < DFF * DM; i += T2) {
        const int k = i / DFF;        // W1 is [20][512] row-major
        const int j = i - k * DFF;
        sW1t[j * DM + k] = W1[i];
        sW2[i] = W2[i];               // W2 is [512][20] row-major, direct copy
    }
    if (tid < DM) { sg2[tid] = g2[tid]; sb2[tid] = b2[tid]; }
    __syncthreads();

    const size_t r0 = (size_t)blockIdx.x * RPB + (size_t)tid * 2;

    // Load two y rows as packed f32x2 pairs (rows are 80B, 16B aligned)
    u64 ya[10], yb[10];
    {
        const ulonglong2* y0 = (const ulonglong2*)(g_y + r0 * DM);
        const ulonglong2* y1 = (const ulonglong2*)(g_y + (r0 + 1) * DM);
        #pragma unroll
        for (int p = 0; p < 5; p++) {
            ulonglong2 a = y0[p]; ya[2*p] = a.x; ya[2*p+1] = a.y;
            ulonglong2 b = y1[p]; yb[2*p] = b.x; yb[2*p+1] = b.y;
        }
    }

    u64 oa[10], ob[10];
    #pragma unroll
    for (int p = 0; p < 10; p++) { oa[p] = 0ULL; ob[p] = 0ULL; }

    const ulonglong2* w1base = (const ulonglong2*)sW1t;
    const ulonglong2* w2base = (const ulonglong2*)sW2;

    // Prologue: start chains for pair 0
    u64 c0, c1, c2, c3;
    chains2(ya, yb, w1base, c0, c1, c2, c3);

    #pragma unroll 1
    for (int j = 0; j < DFF - 2; j += 2) {
        // finalize current pair: relu + splat
        const u64 hha = pack2(hrelu(c0), hrelu(c0));
        const u64 hhb = pack2(hrelu(c1), hrelu(c1));
        const u64 hhc = pack2(hrelu(c2), hrelu(c2));
        const u64 hhd = pack2(hrelu(c3), hrelu(c3));

        // start next pair's chains (independent of hh*) — LDS + fma2 here
        // hide under the down-projection below
        chains2(ya, yb, w1base + (j + 2) * 5, c0, c1, c2, c3);

        // down-projection for current pair
        const ulonglong2* q1 = w2base + j * 5;
        #pragma unroll
        for (int p = 0; p < 5; p++) {
            const ulonglong2 wA = q1[p];
            const ulonglong2 wB = q1[p + 5];
            oa[2*p]   = fma2(hha, wA.x, oa[2*p]);
            oa[2*p+1] = fma2(hha, wA.y, oa[2*p+1]);
            ob[2*p]   = fma2(hhb, wA.x, ob[2*p]);
            ob[2*p+1] = fma2(hhb, wA.y, ob[2*p+1]);
            oa[2*p]   = fma2(hhc, wB.x, oa[2*p]);
            oa[2*p+1] = fma2(hhc, wB.y, oa[2*p+1]);
            ob[2*p]   = fma2(hhd, wB.x, ob[2*p]);
            ob[2*p+1] = fma2(hhd, wB.y, ob[2*p+1]);
        }
    }

    // Epilogue: last pair (j = DFF-2)
    {
        const u64 hha = pack2(hrelu(c0), hrelu(c0));
        const u64 hhb = pack2(hrelu(c1), hrelu(c1));
        const u64 hhc = pack2(hrelu(c2), hrelu(c2));
        const u64 hhd = pack2(hrelu(c3), hrelu(c3));
        const ulonglong2* q1 = w2base + (DFF - 2) * 5;
        #pragma unroll
        for (int p = 0; p < 5; p++) {
            const ulonglong2 wA = q1[p];
            const ulonglong2 wB = q1[p + 5];
            oa[2*p]   = fma2(hha, wA.x, oa[2*p]);
            oa[2*p+1] = fma2(hha, wA.y, oa[2*p+1]);
            ob[2*p]   = fma2(hhb, wA.x, ob[2*p]);
            ob[2*p+1] = fma2(hhb, wA.y, ob[2*p+1]);
            oa[2*p]   = fma2(hhc, wB.x, oa[2*p]);
            oa[2*p+1] = fma2(hhc, wB.y, oa[2*p+1]);
            ob[2*p]   = fma2(hhd, wB.x, ob[2*p]);
            ob[2*p+1] = fma2(hhd, wB.y, ob[2*p+1]);
        }
    }

    ln2_store(ya, oa, sg2, sb2, Out + r0 * DM);
    ln2_store(yb, ob, sg2, sb2, Out + (r0 + 1) * DM);
}

// ======================================================================
// Launch
// ======================================================================
extern "C" void kernel_launch(void* const* d_in, const int* in_sizes, int n_in,
                              void* d_out, int out_size)
{
    (void)in_sizes; (void)n_in; (void)out_size;
    const float* X  = (const float*)d_in[0];
    const float* Wq = (const float*)d_in[1];
    const float* bq = (const float*)d_in[2];
    const float* Wk = (const float*)d_in[3];
    const float* bk = (const float*)d_in[4];
    const float* Wv = (const float*)d_in[5];
    const float* bv = (const float*)d_in[6];
    const float* Wo = (const float*)d_in[7];
    const float* bo = (const float*)d_in[8];
    const float* g1 = (const float*)d_in[9];
    const float* b1 = (const float*)d_in[10];
    const float* W1 = (const float*)d_in[11];
    const float* W2 = (const float*)d_in[12];
    const float* g2 = (const float*)d_in[13];
    const float* b2 = (const float*)d_in[14];
    float* Out = (float*)d_out;

    cudaFuncSetAttribute(k_attn, cudaFuncAttributeMaxDynamicSharedMemorySize, SMEM1);
    cudaFuncSetAttribute(k_ffn, cudaFuncAttributeMaxDynamicSharedMemorySize, SMEM2);

    k_attn<<<NB / GB, T1, SMEM1>>>(X, Wq, bq, Wk, bk, Wv, bv, Wo, bo, g1, b1);
    k_ffn<<<(NB * SQ) / RPB, T2, SMEM2>>>(W1, W2, g2, b2, Out);
}

// round 11
// speedup vs baseline: 1.8066x; 1.7973x over previous
#include <cuda_runtime.h>
#include <cuda_fp16.h>
#include <cstdint>

#define NB   65536
#define SQ   9
#define DM   20
#define NH   4
#define DHD  5
#define DFF  512
#define EPSV 1e-5f

typedef unsigned long long u64;
typedef unsigned int u32;

// scratch: y = LN1(attn_out + x), fp32 (exact, needed for residual)
__device__ __align__(16) float g_y[(size_t)NB * SQ * DM];

// ---------------- f32x2 helpers (k_attn) ----------------
__device__ __forceinline__ u64 fma2(u64 a, u64 b, u64 c) {
    u64 d;
    asm("fma.rn.f32x2 %0, %1, %2, %3;" : "=l"(d) : "l"(a), "l"(b), "l"(c));
    return d;
}
__device__ __forceinline__ float2 unpack2(u64 a) {
    float2 r;
    asm("mov.b64 {%0, %1}, %2;" : "=f"(r.x), "=f"(r.y) : "l"(a));
    return r;
}
__device__ __forceinline__ u64 pack2(float lo, float hi) {
    u64 d;
    asm("mov.b64 %0, {%1, %2};" : "=l"(d)
        : "r"(__float_as_uint(lo)), "r"(__float_as_uint(hi)));
    return d;
}

// ======================================================================
// Kernel 1: attention + LN1 (R7 champion, unchanged)
// ======================================================================
#define GB 16
#define T1 (GB * SQ)  // 144

__global__ void __launch_bounds__(T1) k_attn(
    const float* __restrict__ X,
    const float* __restrict__ Wq, const float* __restrict__ bq,
    const float* __restrict__ Wk, const float* __restrict__ bk,
    const float* __restrict__ Wv, const float* __restrict__ bv,
    const float* __restrict__ Wo, const float* __restrict__ bo,
    const float* __restrict__ g1, const float* __restrict__ b1)
{
    __shared__ __align__(16) float sWq[DM * DM];
    __shared__ __align__(16) float sWk[DM * DM];
    __shared__ __align__(16) float sWv[DM * DM];
    __shared__ __align__(16) float sWo[DM * DM];
    __shared__ __align__(16) float sb[6][DM];
    __shared__ __align__(16) float sK[GB][SQ][DM];
    __shared__ __align__(16) float sV[GB][SQ][DM];
    __shared__ __align__(16) float sM[GB][SQ * DM];

    const int tid = threadIdx.x;
    for (int i = tid; i < DM * DM; i += T1) {
        sWq[i] = Wq[i]; sWk[i] = Wk[i]; sWv[i] = Wv[i]; sWo[i] = Wo[i];
    }
    if (tid < DM) {
        sb[0][tid] = bq[tid]; sb[1][tid] = bk[tid]; sb[2][tid] = bv[tid];
        sb[3][tid] = bo[tid]; sb[4][tid] = g1[tid]; sb[5][tid] = b1[tid];
    }

    const int bl = tid / SQ;
    const int s  = tid - bl * SQ;
    const size_t row = (size_t)(blockIdx.x * GB + bl) * SQ + s;

    float x[DM];
    {
        const float4* xr = (const float4*)(X + row * DM);
        #pragma unroll
        for (int i = 0; i < 5; i++) {
            float4 t = xr[i];
            x[4*i] = t.x; x[4*i+1] = t.y; x[4*i+2] = t.z; x[4*i+3] = t.w;
        }
    }
    __syncthreads();

    u64 q2[10], k2[10], v2[10];
    {
        const u64* bq2 = (const u64*)sb[0];
        const u64* bk2 = (const u64*)sb[1];
        const u64* bv2 = (const u64*)sb[2];
        #pragma unroll
        for (int p = 0; p < 10; p++) { q2[p] = bq2[p]; k2[p] = bk2[p]; v2[p] = bv2[p]; }
    }
    #pragma unroll
    for (int kd = 0; kd < DM; kd++) {
        const u64 x2 = pack2(x[kd], x[kd]);
        const ulonglong2* wq = (const ulonglong2*)(sWq + kd * DM);
        const ulonglong2* wk = (const ulonglong2*)(sWk + kd * DM);
        const ulonglong2* wv = (const ulonglong2*)(sWv + kd * DM);
        #pragma unroll
        for (int p = 0; p < 5; p++) {
            const ulonglong2 a = wq[p];
            q2[2*p]   = fma2(x2, a.x, q2[2*p]);
            q2[2*p+1] = fma2(x2, a.y, q2[2*p+1]);
            const ulonglong2 b = wk[p];
            k2[2*p]   = fma2(x2, b.x, k2[2*p]);
            k2[2*p+1] = fma2(x2, b.y, k2[2*p+1]);
            const ulonglong2 c = wv[p];
            v2[2*p]   = fma2(x2, c.x, v2[2*p]);
            v2[2*p+1] = fma2(x2, c.y, v2[2*p+1]);
        }
    }
    {
        u64* kp = (u64*)(&sK[bl][s][0]);
        u64* vp = (u64*)(&sV[bl][s][0]);
        #pragma unroll
        for (int p = 0; p < 10; p++) { kp[p] = k2[p]; vp[p] = v2[p]; }
    }
    float q[DM];
    #pragma unroll
    for (int p = 0; p < 10; p++) {
        float2 t = unpack2(q2[p]);
        q[2*p] = t.x; q[2*p+1] = t.y;
    }
    __syncthreads();

    #pragma unroll
    for (int h = 0; h < NH; h++) {
        float sc[SQ];
        float mx = -1e30f;
        #pragma unroll
        for (int j = 0; j < SQ; j++) {
            float a = 0.f;
            #pragma unroll
            for (int dh = 0; dh < DHD; dh++)
                a = fmaf(q[h * DHD + dh], sK[bl][j][h * DHD + dh], a);
            a *= (1.0f / 3.0f);
            sc[j] = a;
            mx = fmaxf(mx, a);
        }
        float den = 0.f;
        #pragma unroll
        for (int j = 0; j < SQ; j++) { sc[j] = __expf(sc[j] - mx); den += sc[j]; }
        const float inv = 1.0f / den;
        float ctx[DHD] = {0.f, 0.f, 0.f, 0.f, 0.f};
        #pragma unroll
        for (int j = 0; j < SQ; j++) {
            const float p = sc[j];
            #pragma unroll
            for (int dh = 0; dh < DHD; dh++)
                ctx[dh] = fmaf(p, sV[bl][j][h * DHD + dh], ctx[dh]);
        }
        #pragma unroll
        for (int dh = 0; dh < DHD; dh++)
            sM[bl][h * 45 + dh * 9 + s] = ctx[dh] * inv;
    }
    __syncthreads();

    u64 ao2[10];
    {
        const u64* bo2 = (const u64*)sb[3];
        #pragma unroll
        for (int p = 0; p < 10; p++) ao2[p] = bo2[p];
    }
    #pragma unroll
    for (int kd = 0; kd < DM; kd++) {
        const float m = sM[bl][s * DM + kd];
        const u64 m2 = pack2(m, m);
        const ulonglong2* wo = (const ulonglong2*)(sWo + kd * DM);
        #pragma unroll
        for (int p = 0; p < 5; p++) {
            const ulonglong2 w = wo[p];
            ao2[2*p]   = fma2(m2, w.x, ao2[2*p]);
            ao2[2*p+1] = fma2(m2, w.y, ao2[2*p+1]);
        }
    }
    float r[DM];
    float mean = 0.f;
    #pragma unroll
    for (int p = 0; p < 10; p++) {
        float2 a = unpack2(ao2[p]);
        r[2*p]   = a.x + x[2*p];
        r[2*p+1] = a.y + x[2*p+1];
        mean += r[2*p] + r[2*p+1];
    }
    mean *= (1.0f / 20.0f);
    float var = 0.f;
    #pragma unroll
    for (int d = 0; d < DM; d++) { const float t = r[d] - mean; var = fmaf(t, t, var); }
    var *= (1.0f / 20.0f);
    const float rstd = rsqrtf(var + EPSV);

    float4* yo = (float4*)(g_y + row * DM);
    #pragma unroll
    for (int i = 0; i < 5; i++) {
        float4 t;
        t.x = (r[4*i+0] - mean) * rstd * sb[4][4*i+0] + sb[5][4*i+0];
        t.y = (r[4*i+1] - mean) * rstd * sb[4][4*i+1] + sb[5][4*i+1];
        t.z = (r[4*i+2] - mean) * rstd * sb[4][4*i+2] + sb[5][4*i+2];
        t.w = (r[4*i+3] - mean) * rstd * sb[4][4*i+3] + sb[5][4*i+3];
        yo[i] = t;
    }
}

// ======================================================================
// Kernel 2: FFN via mma.sync.m16n8k16 (fp16 hi/lo 3-product split).
// 512 threads (16 warps), 1 block/SM, 4 passes of 512 rows per block.
// Each warp owns 32 rows end-to-end; GEMM1 D-frags convert in-register
// to GEMM2 A-frags (no shuffles/smem for activations).
// ======================================================================
#define FW      16
#define FTHR    512
#define PASSES  4
#define GRID2   (NB * SQ / (FTHR / 32 * 32 * PASSES))  // 288

// smem byte offsets
#define O_W1H   0                      // [512 n][36 k] f16 (rows 72B, pad)
#define O_W1L   36864
#define O_W2H   73728                  // [24 n][520 k] f16 (rows 1040B, pad)
#define O_W2L   98688
#define O_STAGE 123648                 // [16 w][32 r][28 c] f32
#define SMEMF   (O_STAGE + FW * 32 * 28 * 4)   // 180992

__device__ __forceinline__ void mma16816(float* d,
                                         u32 a0, u32 a1, u32 a2, u32 a3,
                                         u32 b0, u32 b1) {
    asm volatile(
        "mma.sync.aligned.m16n8k16.row.col.f32.f16.f16.f32 "
        "{%0,%1,%2,%3}, {%4,%5,%6,%7}, {%8,%9}, {%0,%1,%2,%3};"
        : "+f"(d[0]), "+f"(d[1]), "+f"(d[2]), "+f"(d[3])
        : "r"(a0), "r"(a1), "r"(a2), "r"(a3), "r"(b0), "r"(b1));
}

__device__ __forceinline__ void split2(float x, float y, u32& h, u32& l) {
    __half2 hh = __floats2half2_rn(x, y);
    float2 hf = __half22float2(hh);
    __half2 ll = __floats2half2_rn(x - hf.x, y - hf.y);
    h = *(u32*)&hh; l = *(u32*)&ll;
}
__device__ __forceinline__ void split2relu(float x, float y, u32& h, u32& l) {
    split2(fmaxf(x, 0.f), fmaxf(y, 0.f), h, l);
}

__global__ void __launch_bounds__(FTHR, 1) k_ffn3(
    const float* __restrict__ W1, const float* __restrict__ W2,
    const float* __restrict__ g2, const float* __restrict__ b2,
    float* __restrict__ Out)
{
    extern __shared__ __align__(16) char sm[];
    const int tid = threadIdx.x;

    // ---- stage W1^T hi/lo: [n=512][k=36 pad] f16, rows 72B ----
    for (int i = tid; i < DFF * 36; i += FTHR) {
        const int n = i / 36, k = i - n * 36;
        const float v = (k < DM) ? W1[k * DFF + n] : 0.f;
        __half h = __float2half_rn(v);
        __half l = __float2half_rn(v - __half2float(h));
        *(__half*)(sm + O_W1H + n * 72 + k * 2) = h;
        *(__half*)(sm + O_W1L + n * 72 + k * 2) = l;
    }
    // ---- stage W2^T hi/lo: [n=24 pad][k=520 pad] f16, rows 1040B ----
    for (int i = tid; i < 24 * 520; i += FTHR) {
        const int n = i / 520, k = i - n * 520;
        const float v = (n < DM && k < DFF) ? W2[k * DM + n] : 0.f;
        __half h = __float2half_rn(v);
        __half l = __float2half_rn(v - __half2float(h));
        *(__half*)(sm + O_W2H + n * 1040 + k * 2) = h;
        *(__half*)(sm + O_W2L + n * 1040 + k * 2) = l;
    }
    __syncthreads();

    const int w    = tid >> 5;
    const int lane = tid & 31;
    const int r    = lane >> 2;
    const int c    = lane & 3;
    float* stg = (float*)(sm + O_STAGE) + w * (32 * 28);

    #pragma unroll 1
    for (int pass = 0; pass < PASSES; pass++) {
        const size_t wbase = ((size_t)blockIdx.x * PASSES + pass) * (size_t)(FW * 32)
                           + (size_t)w * 32;

        // ---- y A-fragments (hi/lo), K padded 20 -> 32 ----
        // per sub m: [0..3] = ktile0 a0..a3; [4],[5] = ktile1 a0,a1 (a2,a3 = 0)
        u32 ah[2][6], al[2][6];
        #pragma unroll
        for (int m = 0; m < 2; m++) {
            const float* y0 = g_y + (wbase + m * 16 + r) * DM;
            const float* y1 = y0 + 8 * DM;
            float2 p;
            p = *(const float2*)(y0 + 2 * c);     split2(p.x, p.y, ah[m][0], al[m][0]);
            p = *(const float2*)(y1 + 2 * c);     split2(p.x, p.y, ah[m][1], al[m][1]);
            p = *(const float2*)(y0 + 2 * c + 8); split2(p.x, p.y, ah[m][2], al[m][2]);
            p = *(const float2*)(y1 + 2 * c + 8); split2(p.x, p.y, ah[m][3], al[m][3]);
            if (c < 2) {
                p = *(const float2*)(y0 + 16 + 2 * c); split2(p.x, p.y, ah[m][4], al[m][4]);
                p = *(const float2*)(y1 + 16 + 2 * c); split2(p.x, p.y, ah[m][5], al[m][5]);
            } else {
                ah[m][4] = al[m][4] = ah[m][5] = al[m][5] = 0u;
            }
        }

        float d2[3][2][4];
        #pragma unroll
        for (int n = 0; n < 3; n++)
            #pragma unroll
            for (int m = 0; m < 2; m++)
                #pragma unroll
                for (int i = 0; i < 4; i++) d2[n][m][i] = 0.f;

        #pragma unroll 1
        for (int ch = 0; ch < 16; ch++) {
            // ---- GEMM1: D1[32 rows x 32 n] over K=32 (2 ktiles) ----
            float d1[4][2][4];
            #pragma unroll
            for (int n = 0; n < 4; n++)
                #pragma unroll
                for (int m = 0; m < 2; m++)
                    #pragma unroll
                    for (int i = 0; i < 4; i++) d1[n][m][i] = 0.f;

            #pragma unroll
            for (int kt = 0; kt < 2; kt++) {
                #pragma unroll
                for (int nt = 0; nt < 4; nt++) {
                    const u32 boff = (u32)((ch * 32 + nt * 8 + r) * 72 + kt * 32 + c * 4);
                    const u32 bh0 = *(const u32*)(sm + O_W1H + boff);
                    const u32 bh1 = *(const u32*)(sm + O_W1H + boff + 16);
                    const u32 bl0 = *(const u32*)(sm + O_W1L + boff);
                    const u32 bl1 = *(const u32*)(sm + O_W1L + boff + 16);
                    #pragma unroll
                    for (int m = 0; m < 2; m++) {
                        const u32 A0h = kt ? ah[m][4] : ah[m][0];
                        const u32 A1h = kt ? ah[m][5] : ah[m][1];
                        const u32 A2h = kt ? 0u       : ah[m][2];
                        const u32 A3h = kt ? 0u       : ah[m][3];
                        const u32 A0l = kt ? al[m][4] : al[m][0];
                        const u32 A1l = kt ? al[m][5] : al[m][1];
                        const u32 A2l = kt ? 0u       : al[m][2];
                        const u32 A3l = kt ? 0u       : al[m][3];
                        mma16816(d1[nt][m], A0h, A1h, A2h, A3h, bh0, bh1);  // yh*wh
                        mma16816(d1[nt][m], A0h, A1h, A2h, A3h, bl0, bl1);  // yh*wl
                        mma16816(d1[nt][m], A0l, A1l, A2l, A3l, bh0, bh1);  // yl*wh
                    }
                }
            }

            // ---- per k-subtile: convert D1 -> A2 frags, then GEMM2 ----
            #pragma unroll
            for (int kt2 = 0; kt2 < 2; kt2++) {
                u32 fh[2][4], fl[2][4];
                #pragma unroll
                for (int m = 0; m < 2; m++) {
                    const float* dA = d1[2 * kt2][m];      // -> a0, a1
                    const float* dB = d1[2 * kt2 + 1][m];  // -> a2, a3
                    split2relu(dA[0], dA[1], fh[m][0], fl[m][0]);
                    split2relu(dA[2], dA[3], fh[m][1], fl[m][1]);
                    split2relu(dB[0], dB[1], fh[m][2], fl[m][2]);
                    split2relu(dB[2], dB[3], fh[m][3], fl[m][3]);
                }
                #pragma unroll
                for (int nt2 = 0; nt2 < 3; nt2++) {
                    const u32 boff = (u32)((nt2 * 8 + r) * 1040
                                   + (ch * 32 + kt2 * 16) * 2 + c * 4);
                    const u32 bh0 = *(const u32*)(sm + O_W2H + boff);
                    const u32 bh1 = *(const u32*)(sm + O_W2H + boff + 16);
                    const u32 bl0 = *(const u32*)(sm + O_W2L + boff);
                    const u32 bl1 = *(const u32*)(sm + O_W2L + boff + 16);
                    #pragma unroll
                    for (int m = 0; m < 2; m++) {
                        mma16816(d2[nt2][m], fh[m][0], fh[m][1], fh[m][2], fh[m][3], bh0, bh1);
                        mma16816(d2[nt2][m], fh[m][0], fh[m][1], fh[m][2], fh[m][3], bl0, bl1);
                        mma16816(d2[nt2][m], fl[m][0], fl[m][1], fl[m][2], fl[m][3], bh0, bh1);
                    }
                }
            }
        }

        // ---- epilogue: D2 frags -> staging -> per-lane residual + LN2 ----
        #pragma unroll
        for (int nt2 = 0; nt2 < 3; nt2++) {
            #pragma unroll
            for (int m = 0; m < 2; m++) {
                float* s0 = stg + (m * 16 + r) * 28 + nt2 * 8 + 2 * c;
                s0[0]  = d2[nt2][m][0];
                s0[1]  = d2[nt2][m][1];
                float* s1 = s0 + 8 * 28;
                s1[0]  = d2[nt2][m][2];
                s1[1]  = d2[nt2][m][3];
            }
        }
        __syncwarp();

        {
            const size_t gr = wbase + lane;
            const float* yr = g_y + gr * DM;
            const float* fr = stg + lane * 28;
            float rr[DM];
            float mean = 0.f;
            #pragma unroll
            for (int d = 0; d < DM; d++) {
                rr[d] = yr[d] + fr[d];
                mean += rr[d];
            }
            mean *= (1.0f / 20.0f);
            float var = 0.f;
            #pragma unroll
            for (int d = 0; d < DM; d++) { const float t = rr[d] - mean; var = fmaf(t, t, var); }
            var *= (1.0f / 20.0f);
            const float rstd = rsqrtf(var + EPSV);
            float4* o4 = (float4*)(Out + gr * DM);
            #pragma unroll
            for (int i = 0; i < 5; i++) {
                float4 o;
                o.x = (rr[4*i+0] - mean) * rstd * g2[4*i+0] + b2[4*i+0];
                o.y = (rr[4*i+1] - mean) * rstd * g2[4*i+1] + b2[4*i+1];
                o.z = (rr[4*i+2] - mean) * rstd * g2[4*i+2] + b2[4*i+2];
                o.w = (rr[4*i+3] - mean) * rstd * g2[4*i+3] + b2[4*i+3];
                o4[i] = o;
            }
        }
        __syncwarp();
    }
}

// ======================================================================
// Launch
// ======================================================================
extern "C" void kernel_launch(void* const* d_in, const int* in_sizes, int n_in,
                              void* d_out, int out_size)
{
    (void)in_sizes; (void)n_in; (void)out_size;
    const float* X  = (const float*)d_in[0];
    const float* Wq = (const float*)d_in[1];
    const float* bq = (const float*)d_in[2];
    const float* Wk = (const float*)d_in[3];
    const float* bk = (const float*)d_in[4];
    const float* Wv = (const float*)d_in[5];
    const float* bv = (const float*)d_in[6];
    const float* Wo = (const float*)d_in[7];
    const float* bo = (const float*)d_in[8];
    const float* g1 = (const float*)d_in[9];
    const float* b1 = (const float*)d_in[10];
    const float* W1 = (const float*)d_in[11];
    const float* W2 = (const float*)d_in[12];
    const float* g2 = (const float*)d_in[13];
    const float* b2 = (const float*)d_in[14];
    float* Out = (float*)d_out;

    cudaFuncSetAttribute(k_ffn3, cudaFuncAttributeMaxDynamicSharedMemorySize, SMEMF);

    k_attn<<<NB / GB, T1>>>(X, Wq, bq, Wk, bk, Wv, bv, Wo, bo, g1, b1);
    k_ffn3<<<GRID2, FTHR, SMEMF>>>(W1, W2, g2, b2, Out);
}

// round 12
// speedup vs baseline: 2.0942x; 1.1592x over previous
#include <cuda_runtime.h>
#include <cuda_fp16.h>
#include <cstdint>

#define NB   65536
#define SQ   9
#define DM   20
#define NH   4
#define DHD  5
#define DFF  512
#define EPSV 1e-5f

typedef unsigned long long u64;
typedef unsigned int u32;

// scratch: y = LN1(attn_out + x), fp32 (exact, needed for residual)
__device__ __align__(16) float g_y[(size_t)NB * SQ * DM];

// ---------------- f32x2 helpers (k_attn) ----------------
__device__ __forceinline__ u64 fma2(u64 a, u64 b, u64 c) {
    u64 d;
    asm("fma.rn.f32x2 %0, %1, %2, %3;" : "=l"(d) : "l"(a), "l"(b), "l"(c));
    return d;
}
__device__ __forceinline__ float2 unpack2(u64 a) {
    float2 r;
    asm("mov.b64 {%0, %1}, %2;" : "=f"(r.x), "=f"(r.y) : "l"(a));
    return r;
}
__device__ __forceinline__ u64 pack2(float lo, float hi) {
    u64 d;
    asm("mov.b64 %0, {%1, %2};" : "=l"(d)
        : "r"(__float_as_uint(lo)), "r"(__float_as_uint(hi)));
    return d;
}

// ======================================================================
// Kernel 1: attention + LN1 (champion, unchanged)
// ======================================================================
#define GB 16
#define T1 (GB * SQ)  // 144

__global__ void __launch_bounds__(T1) k_attn(
    const float* __restrict__ X,
    const float* __restrict__ Wq, const float* __restrict__ bq,
    const float* __restrict__ Wk, const float* __restrict__ bk,
    const float* __restrict__ Wv, const float* __restrict__ bv,
    const float* __restrict__ Wo, const float* __restrict__ bo,
    const float* __restrict__ g1, const float* __restrict__ b1)
{
    __shared__ __align__(16) float sWq[DM * DM];
    __shared__ __align__(16) float sWk[DM * DM];
    __shared__ __align__(16) float sWv[DM * DM];
    __shared__ __align__(16) float sWo[DM * DM];
    __shared__ __align__(16) float sb[6][DM];
    __shared__ __align__(16) float sK[GB][SQ][DM];
    __shared__ __align__(16) float sV[GB][SQ][DM];
    __shared__ __align__(16) float sM[GB][SQ * DM];

    const int tid = threadIdx.x;
    for (int i = tid; i < DM * DM; i += T1) {
        sWq[i] = Wq[i]; sWk[i] = Wk[i]; sWv[i] = Wv[i]; sWo[i] = Wo[i];
    }
    if (tid < DM) {
        sb[0][tid] = bq[tid]; sb[1][tid] = bk[tid]; sb[2][tid] = bv[tid];
        sb[3][tid] = bo[tid]; sb[4][tid] = g1[tid]; sb[5][tid] = b1[tid];
    }

    const int bl = tid / SQ;
    const int s  = tid - bl * SQ;
    const size_t row = (size_t)(blockIdx.x * GB + bl) * SQ + s;

    float x[DM];
    {
        const float4* xr = (const float4*)(X + row * DM);
        #pragma unroll
        for (int i = 0; i < 5; i++) {
            float4 t = xr[i];
            x[4*i] = t.x; x[4*i+1] = t.y; x[4*i+2] = t.z; x[4*i+3] = t.w;
        }
    }
    __syncthreads();

    u64 q2[10], k2[10], v2[10];
    {
        const u64* bq2 = (const u64*)sb[0];
        const u64* bk2 = (const u64*)sb[1];
        const u64* bv2 = (const u64*)sb[2];
        #pragma unroll
        for (int p = 0; p < 10; p++) { q2[p] = bq2[p]; k2[p] = bk2[p]; v2[p] = bv2[p]; }
    }
    #pragma unroll
    for (int kd = 0; kd < DM; kd++) {
        const u64 x2 = pack2(x[kd], x[kd]);
        const ulonglong2* wq = (const ulonglong2*)(sWq + kd * DM);
        const ulonglong2* wk = (const ulonglong2*)(sWk + kd * DM);
        const ulonglong2* wv = (const ulonglong2*)(sWv + kd * DM);
        #pragma unroll
        for (int p = 0; p < 5; p++) {
            const ulonglong2 a = wq[p];
            q2[2*p]   = fma2(x2, a.x, q2[2*p]);
            q2[2*p+1] = fma2(x2, a.y, q2[2*p+1]);
            const ulonglong2 b = wk[p];
            k2[2*p]   = fma2(x2, b.x, k2[2*p]);
            k2[2*p+1] = fma2(x2, b.y, k2[2*p+1]);
            const ulonglong2 c = wv[p];
            v2[2*p]   = fma2(x2, c.x, v2[2*p]);
            v2[2*p+1] = fma2(x2, c.y, v2[2*p+1]);
        }
    }
    {
        u64* kp = (u64*)(&sK[bl][s][0]);
        u64* vp = (u64*)(&sV[bl][s][0]);
        #pragma unroll
        for (int p = 0; p < 10; p++) { kp[p] = k2[p]; vp[p] = v2[p]; }
    }
    float q[DM];
    #pragma unroll
    for (int p = 0; p < 10; p++) {
        float2 t = unpack2(q2[p]);
        q[2*p] = t.x; q[2*p+1] = t.y;
    }
    __syncthreads();

    #pragma unroll
    for (int h = 0; h < NH; h++) {
        float sc[SQ];
        float mx = -1e30f;
        #pragma unroll
        for (int j = 0; j < SQ; j++) {
            float a = 0.f;
            #pragma unroll
            for (int dh = 0; dh < DHD; dh++)
                a = fmaf(q[h * DHD + dh], sK[bl][j][h * DHD + dh], a);
            a *= (1.0f / 3.0f);
            sc[j] = a;
            mx = fmaxf(mx, a);
        }
        float den = 0.f;
        #pragma unroll
        for (int j = 0; j < SQ; j++) { sc[j] = __expf(sc[j] - mx); den += sc[j]; }
        const float inv = 1.0f / den;
        float ctx[DHD] = {0.f, 0.f, 0.f, 0.f, 0.f};
        #pragma unroll
        for (int j = 0; j < SQ; j++) {
            const float p = sc[j];
            #pragma unroll
            for (int dh = 0; dh < DHD; dh++)
                ctx[dh] = fmaf(p, sV[bl][j][h * DHD + dh], ctx[dh]);
        }
        #pragma unroll
        for (int dh = 0; dh < DHD; dh++)
            sM[bl][h * 45 + dh * 9 + s] = ctx[dh] * inv;
    }
    __syncthreads();

    u64 ao2[10];
    {
        const u64* bo2 = (const u64*)sb[3];
        #pragma unroll
        for (int p = 0; p < 10; p++) ao2[p] = bo2[p];
    }
    #pragma unroll
    for (int kd = 0; kd < DM; kd++) {
        const float m = sM[bl][s * DM + kd];
        const u64 m2 = pack2(m, m);
        const ulonglong2* wo = (const ulonglong2*)(sWo + kd * DM);
        #pragma unroll
        for (int p = 0; p < 5; p++) {
            const ulonglong2 w = wo[p];
            ao2[2*p]   = fma2(m2, w.x, ao2[2*p]);
            ao2[2*p+1] = fma2(m2, w.y, ao2[2*p+1]);
        }
    }
    float r[DM];
    float mean = 0.f;
    #pragma unroll
    for (int p = 0; p < 10; p++) {
        float2 a = unpack2(ao2[p]);
        r[2*p]   = a.x + x[2*p];
        r[2*p+1] = a.y + x[2*p+1];
        mean += r[2*p] + r[2*p+1];
    }
    mean *= (1.0f / 20.0f);
    float var = 0.f;
    #pragma unroll
    for (int d = 0; d < DM; d++) { const float t = r[d] - mean; var = fmaf(t, t, var); }
    var *= (1.0f / 20.0f);
    const float rstd = rsqrtf(var + EPSV);

    float4* yo = (float4*)(g_y + row * DM);
    #pragma unroll
    for (int i = 0; i < 5; i++) {
        float4 t;
        t.x = (r[4*i+0] - mean) * rstd * sb[4][4*i+0] + sb[5][4*i+0];
        t.y = (r[4*i+1] - mean) * rstd * sb[4][4*i+1] + sb[5][4*i+1];
        t.z = (r[4*i+2] - mean) * rstd * sb[4][4*i+2] + sb[5][4*i+2];
        t.w = (r[4*i+3] - mean) * rstd * sb[4][4*i+3] + sb[5][4*i+3];
        yo[i] = t;
    }
}

// ======================================================================
// Kernel 2: FFN via mma.sync (fp16 hi/lo split).
// GEMM1: 3-product (yh*wh + yh*wl + yl*wh), k-tail via m16n8k8.
// GEMM2: 2-product (fh*wh + fh*wl) — activation-lo dropped (norm-rel
//        error contribution ~1e-4, metric is norm-based).
// 512 threads (16 warps), 1 block/SM, 4 passes of 512 rows per block.
// ======================================================================
#define FW      16
#define FTHR    512
#define PASSES  4
#define GRID2   (NB * SQ / (FTHR / 32 * 32 * PASSES))  // 288

// smem byte offsets
#define O_W1H   0                      // [512 n][36 k] f16 (rows 72B, pad)
#define O_W1L   36864
#define O_W2H   73728                  // [24 n][520 k] f16 (rows 1040B, pad)
#define O_W2L   98688
#define O_STAGE 123648                 // [16 w][32 r][28 c] f32
#define SMEMF   (O_STAGE + FW * 32 * 28 * 4)   // 180992

__device__ __forceinline__ void mma16816(float* d,
                                         u32 a0, u32 a1, u32 a2, u32 a3,
                                         u32 b0, u32 b1) {
    asm volatile(
        "mma.sync.aligned.m16n8k16.row.col.f32.f16.f16.f32 "
        "{%0,%1,%2,%3}, {%4,%5,%6,%7}, {%8,%9}, {%0,%1,%2,%3};"
        : "+f"(d[0]), "+f"(d[1]), "+f"(d[2]), "+f"(d[3])
        : "r"(a0), "r"(a1), "r"(a2), "r"(a3), "r"(b0), "r"(b1));
}
__device__ __forceinline__ void mma1688(float* d, u32 a0, u32 a1, u32 b0) {
    asm volatile(
        "mma.sync.aligned.m16n8k8.row.col.f32.f16.f16.f32 "
        "{%0,%1,%2,%3}, {%4,%5}, {%6}, {%0,%1,%2,%3};"
        : "+f"(d[0]), "+f"(d[1]), "+f"(d[2]), "+f"(d[3])
        : "r"(a0), "r"(a1), "r"(b0));
}

__device__ __forceinline__ void split2(float x, float y, u32& h, u32& l) {
    __half2 hh = __floats2half2_rn(x, y);
    float2 hf = __half22float2(hh);
    __half2 ll = __floats2half2_rn(x - hf.x, y - hf.y);
    h = *(u32*)&hh; l = *(u32*)&ll;
}
__device__ __forceinline__ u32 pack2relu(float x, float y) {
    __half2 hh = __floats2half2_rn(fmaxf(x, 0.f), fmaxf(y, 0.f));
    return *(u32*)&hh;
}

__global__ void __launch_bounds__(FTHR, 1) k_ffn3(
    const float* __restrict__ W1, const float* __restrict__ W2,
    const float* __restrict__ g2, const float* __restrict__ b2,
    float* __restrict__ Out)
{
    extern __shared__ __align__(16) char sm[];
    const int tid = threadIdx.x;

    // ---- stage W1^T hi/lo: [n=512][k=36 pad] f16, rows 72B ----
    for (int i = tid; i < DFF * 36; i += FTHR) {
        const int n = i / 36, k = i - n * 36;
        const float v = (k < DM) ? W1[k * DFF + n] : 0.f;
        __half h = __float2half_rn(v);
        __half l = __float2half_rn(v - __half2float(h));
        *(__half*)(sm + O_W1H + n * 72 + k * 2) = h;
        *(__half*)(sm + O_W1L + n * 72 + k * 2) = l;
    }
    // ---- stage W2^T hi/lo: [n=24 pad][k=520 pad] f16, rows 1040B ----
    for (int i = tid; i < 24 * 520; i += FTHR) {
        const int n = i / 520, k = i - n * 520;
        const float v = (n < DM && k < DFF) ? W2[k * DM + n] : 0.f;
        __half h = __float2half_rn(v);
        __half l = __float2half_rn(v - __half2float(h));
        *(__half*)(sm + O_W2H + n * 1040 + k * 2) = h;
        *(__half*)(sm + O_W2L + n * 1040 + k * 2) = l;
    }
    __syncthreads();

    const int w    = tid >> 5;
    const int lane = tid & 31;
    const int r    = lane >> 2;
    const int c    = lane & 3;
    float* stg = (float*)(sm + O_STAGE) + w * (32 * 28);

    #pragma unroll 1
    for (int pass = 0; pass < PASSES; pass++) {
        const size_t wbase = ((size_t)blockIdx.x * PASSES + pass) * (size_t)(FW * 32)
                           + (size_t)w * 32;

        // ---- y A-fragments (hi/lo), K padded 20 -> 32 ----
        // [0..3] = ktile0 (k16); [4],[5] = k-tail (k8, valid c<2)
        u32 ah[2][6], al[2][6];
        #pragma unroll
        for (int m = 0; m < 2; m++) {
            const float* y0 = g_y + (wbase + m * 16 + r) * DM;
            const float* y1 = y0 + 8 * DM;
            float2 p;
            p = *(const float2*)(y0 + 2 * c);     split2(p.x, p.y, ah[m][0], al[m][0]);
            p = *(const float2*)(y1 + 2 * c);     split2(p.x, p.y, ah[m][1], al[m][1]);
            p = *(const float2*)(y0 + 2 * c + 8); split2(p.x, p.y, ah[m][2], al[m][2]);
            p = *(const float2*)(y1 + 2 * c + 8); split2(p.x, p.y, ah[m][3], al[m][3]);
            if (c < 2) {
                p = *(const float2*)(y0 + 16 + 2 * c); split2(p.x, p.y, ah[m][4], al[m][4]);
                p = *(const float2*)(y1 + 16 + 2 * c); split2(p.x, p.y, ah[m][5], al[m][5]);
            } else {
                ah[m][4] = al[m][4] = ah[m][5] = al[m][5] = 0u;
            }
        }

        float d2[3][2][4];
        #pragma unroll
        for (int n = 0; n < 3; n++)
            #pragma unroll
            for (int m = 0; m < 2; m++)
                #pragma unroll
                for (int i = 0; i < 4; i++) d2[n][m][i] = 0.f;

        #pragma unroll 1
        for (int ch = 0; ch < 16; ch++) {
            // ---- GEMM1: D1[32 rows x 32 n], K = 16 (k16) + 8 (k8 tail) ----
            float d1[4][2][4];
            #pragma unroll
            for (int n = 0; n < 4; n++)
                #pragma unroll
                for (int m = 0; m < 2; m++)
                    #pragma unroll
                    for (int i = 0; i < 4; i++) d1[n][m][i] = 0.f;

            #pragma unroll
            for (int nt = 0; nt < 4; nt++) {
                // k-tile 0 (k = 0..15), 3 products k16
                const u32 boff = (u32)((ch * 32 + nt * 8 + r) * 72 + c * 4);
                const u32 bh0 = *(const u32*)(sm + O_W1H + boff);
                const u32 bh1 = *(const u32*)(sm + O_W1H + boff + 16);
                const u32 bl0 = *(const u32*)(sm + O_W1L + boff);
                const u32 bl1 = *(const u32*)(sm + O_W1L + boff + 16);
                // k-tail (k = 16..23, valid 16..19), 3 products k8
                const u32 toff = boff + 32;
                const u32 th0 = *(const u32*)(sm + O_W1H + toff);
                const u32 tl0 = *(const u32*)(sm + O_W1L + toff);
                #pragma unroll
                for (int m = 0; m < 2; m++) {
                    mma16816(d1[nt][m], ah[m][0], ah[m][1], ah[m][2], ah[m][3], bh0, bh1);
                    mma16816(d1[nt][m], ah[m][0], ah[m][1], ah[m][2], ah[m][3], bl0, bl1);
                    mma16816(d1[nt][m], al[m][0], al[m][1], al[m][2], al[m][3], bh0, bh1);
                    mma1688(d1[nt][m], ah[m][4], ah[m][5], th0);
                    mma1688(d1[nt][m], ah[m][4], ah[m][5], tl0);
                    mma1688(d1[nt][m], al[m][4], al[m][5], th0);
                }
            }

            // ---- per k-subtile: relu-pack D1 -> A2 frags (hi only), GEMM2 ----
            #pragma unroll
            for (int kt2 = 0; kt2 < 2; kt2++) {
                u32 fh[2][4];
                #pragma unroll
                for (int m = 0; m < 2; m++) {
                    const float* dA = d1[2 * kt2][m];      // -> a0, a1
                    const float* dB = d1[2 * kt2 + 1][m];  // -> a2, a3
                    fh[m][0] = pack2relu(dA[0], dA[1]);
                    fh[m][1] = pack2relu(dA[2], dA[3]);
                    fh[m][2] = pack2relu(dB[0], dB[1]);
                    fh[m][3] = pack2relu(dB[2], dB[3]);
                }
                #pragma unroll
                for (int nt2 = 0; nt2 < 3; nt2++) {
                    const u32 boff = (u32)((nt2 * 8 + r) * 1040
                                   + (ch * 32 + kt2 * 16) * 2 + c * 4);
                    const u32 bh0 = *(const u32*)(sm + O_W2H + boff);
                    const u32 bh1 = *(const u32*)(sm + O_W2H + boff + 16);
                    const u32 bl0 = *(const u32*)(sm + O_W2L + boff);
                    const u32 bl1 = *(const u32*)(sm + O_W2L + boff + 16);
                    #pragma unroll
                    for (int m = 0; m < 2; m++) {
                        mma16816(d2[nt2][m], fh[m][0], fh[m][1], fh[m][2], fh[m][3], bh0, bh1);
                        mma16816(d2[nt2][m], fh[m][0], fh[m][1], fh[m][2], fh[m][3], bl0, bl1);
                    }
                }
            }
        }

        // ---- epilogue: D2 frags -> staging -> per-lane residual + LN2 ----
        #pragma unroll
        for (int nt2 = 0; nt2 < 3; nt2++) {
            #pragma unroll
            for (int m = 0; m < 2; m++) {
                float* s0 = stg + (m * 16 + r) * 28 + nt2 * 8 + 2 * c;
                s0[0]  = d2[nt2][m][0];
                s0[1]  = d2[nt2][m][1];
                float* s1 = s0 + 8 * 28;
                s1[0]  = d2[nt2][m][2];
                s1[1]  = d2[nt2][m][3];
            }
        }
        __syncwarp();

        {
            const size_t gr = wbase + lane;
            const float* yr = g_y + gr * DM;
            const float* fr = stg + lane * 28;
            float rr[DM];
            float mean = 0.f;
            #pragma unroll
            for (int d = 0; d < DM; d++) {
                rr[d] = yr[d] + fr[d];
                mean += rr[d];
            }
            mean *= (1.0f / 20.0f);
            float var = 0.f;
            #pragma unroll
            for (int d = 0; d < DM; d++) { const float t = rr[d] - mean; var = fmaf(t, t, var); }
            var *= (1.0f / 20.0f);
            const float rstd = rsqrtf(var + EPSV);
            float4* o4 = (float4*)(Out + gr * DM);
            #pragma unroll
            for (int i = 0; i < 5; i++) {
                float4 o;
                o.x = (rr[4*i+0] - mean) * rstd * g2[4*i+0] + b2[4*i+0];
                o.y = (rr[4*i+1] - mean) * rstd * g2[4*i+1] + b2[4*i+1];
                o.z = (rr[4*i+2] - mean) * rstd * g2[4*i+2] + b2[4*i+2];
                o.w = (rr[4*i+3] - mean) * rstd * g2[4*i+3] + b2[4*i+3];
                o4[i] = o;
            }
        }
        __syncwarp();
    }
}

// ======================================================================
// Launch
// ======================================================================
extern "C" void kernel_launch(void* const* d_in, const int* in_sizes, int n_in,
                              void* d_out, int out_size)
{
    (void)in_sizes; (void)n_in; (void)out_size;
    const float* X  = (const float*)d_in[0];
    const float* Wq = (const float*)d_in[1];
    const float* bq = (const float*)d_in[2];
    const float* Wk = (const float*)d_in[3];
    const float* bk = (const float*)d_in[4];
    const float* Wv = (const float*)d_in[5];
    const float* bv = (const float*)d_in[6];
    const float* Wo = (const float*)d_in[7];
    const float* bo = (const float*)d_in[8];
    const float* g1 = (const float*)d_in[9];
    const float* b1 = (const float*)d_in[10];
    const float* W1 = (const float*)d_in[11];
    const float* W2 = (const float*)d_in[12];
    const float* g2 = (const float*)d_in[13];
    const float* b2 = (const float*)d_in[14];
    float* Out = (float*)d_out;

    cudaFuncSetAttribute(k_ffn3, cudaFuncAttributeMaxDynamicSharedMemorySize, SMEMF);

    k_attn<<<NB / GB, T1>>>(X, Wq, bq, Wk, bk, Wv, bv, Wo, bo, g1, b1);
    k_ffn3<<<GRID2, FTHR, SMEMF>>>(W1, W2, g2, b2, Out);
}

// round 13
// speedup vs baseline: 2.9997x; 1.4324x over previous
#include <cuda_runtime.h>
#include <cuda_fp16.h>
#include <cstdint>

#define NB   65536
#define SQ   9
#define DM   20
#define NH   4
#define DHD  5
#define DFF  512
#define EPSV 1e-5f

typedef unsigned long long u64;
typedef unsigned int u32;

// scratch: y = LN1(attn_out + x), fp32 (exact, needed for residual)
__device__ __align__(16) float g_y[(size_t)NB * SQ * DM];

// ---------------- f32x2 helpers (k_attn) ----------------
__device__ __forceinline__ u64 fma2(u64 a, u64 b, u64 c) {
    u64 d;
    asm("fma.rn.f32x2 %0, %1, %2, %3;" : "=l"(d) : "l"(a), "l"(b), "l"(c));
    return d;
}
__device__ __forceinline__ float2 unpack2(u64 a) {
    float2 r;
    asm("mov.b64 {%0, %1}, %2;" : "=f"(r.x), "=f"(r.y) : "l"(a));
    return r;
}
__device__ __forceinline__ u64 pack2(float lo, float hi) {
    u64 d;
    asm("mov.b64 %0, {%1, %2};" : "=l"(d)
        : "r"(__float_as_uint(lo)), "r"(__float_as_uint(hi)));
    return d;
}

// ======================================================================
// Kernel 1: attention + LN1 (champion, unchanged)
// ======================================================================
#define GB 16
#define T1 (GB * SQ)  // 144

__global__ void __launch_bounds__(T1) k_attn(
    const float* __restrict__ X,
    const float* __restrict__ Wq, const float* __restrict__ bq,
    const float* __restrict__ Wk, const float* __restrict__ bk,
    const float* __restrict__ Wv, const float* __restrict__ bv,
    const float* __restrict__ Wo, const float* __restrict__ bo,
    const float* __restrict__ g1, const float* __restrict__ b1)
{
    __shared__ __align__(16) float sWq[DM * DM];
    __shared__ __align__(16) float sWk[DM * DM];
    __shared__ __align__(16) float sWv[DM * DM];
    __shared__ __align__(16) float sWo[DM * DM];
    __shared__ __align__(16) float sb[6][DM];
    __shared__ __align__(16) float sK[GB][SQ][DM];
    __shared__ __align__(16) float sV[GB][SQ][DM];
    __shared__ __align__(16) float sM[GB][SQ * DM];

    const int tid = threadIdx.x;
    for (int i = tid; i < DM * DM; i += T1) {
        sWq[i] = Wq[i]; sWk[i] = Wk[i]; sWv[i] = Wv[i]; sWo[i] = Wo[i];
    }
    if (tid < DM) {
        sb[0][tid] = bq[tid]; sb[1][tid] = bk[tid]; sb[2][tid] = bv[tid];
        sb[3][tid] = bo[tid]; sb[4][tid] = g1[tid]; sb[5][tid] = b1[tid];
    }

    const int bl = tid / SQ;
    const int s  = tid - bl * SQ;
    const size_t row = (size_t)(blockIdx.x * GB + bl) * SQ + s;

    float x[DM];
    {
        const float4* xr = (const float4*)(X + row * DM);
        #pragma unroll
        for (int i = 0; i < 5; i++) {
            float4 t = xr[i];
            x[4*i] = t.x; x[4*i+1] = t.y; x[4*i+2] = t.z; x[4*i+3] = t.w;
        }
    }
    __syncthreads();

    u64 q2[10], k2[10], v2[10];
    {
        const u64* bq2 = (const u64*)sb[0];
        const u64* bk2 = (const u64*)sb[1];
        const u64* bv2 = (const u64*)sb[2];
        #pragma unroll
        for (int p = 0; p < 10; p++) { q2[p] = bq2[p]; k2[p] = bk2[p]; v2[p] = bv2[p]; }
    }
    #pragma unroll
    for (int kd = 0; kd < DM; kd++) {
        const u64 x2 = pack2(x[kd], x[kd]);
        const ulonglong2* wq = (const ulonglong2*)(sWq + kd * DM);
        const ulonglong2* wk = (const ulonglong2*)(sWk + kd * DM);
        const ulonglong2* wv = (const ulonglong2*)(sWv + kd * DM);
        #pragma unroll
        for (int p = 0; p < 5; p++) {
            const ulonglong2 a = wq[p];
            q2[2*p]   = fma2(x2, a.x, q2[2*p]);
            q2[2*p+1] = fma2(x2, a.y, q2[2*p+1]);
            const ulonglong2 b = wk[p];
            k2[2*p]   = fma2(x2, b.x, k2[2*p]);
            k2[2*p+1] = fma2(x2, b.y, k2[2*p+1]);
            const ulonglong2 c = wv[p];
            v2[2*p]   = fma2(x2, c.x, v2[2*p]);
            v2[2*p+1] = fma2(x2, c.y, v2[2*p+1]);
        }
    }
    {
        u64* kp = (u64*)(&sK[bl][s][0]);
        u64* vp = (u64*)(&sV[bl][s][0]);
        #pragma unroll
        for (int p = 0; p < 10; p++) { kp[p] = k2[p]; vp[p] = v2[p]; }
    }
    float q[DM];
    #pragma unroll
    for (int p = 0; p < 10; p++) {
        float2 t = unpack2(q2[p]);
        q[2*p] = t.x; q[2*p+1] = t.y;
    }
    __syncthreads();

    #pragma unroll
    for (int h = 0; h < NH; h++) {
        float sc[SQ];
        float mx = -1e30f;
        #pragma unroll
        for (int j = 0; j < SQ; j++) {
            float a = 0.f;
            #pragma unroll
            for (int dh = 0; dh < DHD; dh++)
                a = fmaf(q[h * DHD + dh], sK[bl][j][h * DHD + dh], a);
            a *= (1.0f / 3.0f);
            sc[j] = a;
            mx = fmaxf(mx, a);
        }
        float den = 0.f;
        #pragma unroll
        for (int j = 0; j < SQ; j++) { sc[j] = __expf(sc[j] - mx); den += sc[j]; }
        const float inv = 1.0f / den;
        float ctx[DHD] = {0.f, 0.f, 0.f, 0.f, 0.f};
        #pragma unroll
        for (int j = 0; j < SQ; j++) {
            const float p = sc[j];
            #pragma unroll
            for (int dh = 0; dh < DHD; dh++)
                ctx[dh] = fmaf(p, sV[bl][j][h * DHD + dh], ctx[dh]);
        }
        #pragma unroll
        for (int dh = 0; dh < DHD; dh++)
            sM[bl][h * 45 + dh * 9 + s] = ctx[dh] * inv;
    }
    __syncthreads();

    u64 ao2[10];
    {
        const u64* bo2 = (const u64*)sb[3];
        #pragma unroll
        for (int p = 0; p < 10; p++) ao2[p] = bo2[p];
    }
    #pragma unroll
    for (int kd = 0; kd < DM; kd++) {
        const float m = sM[bl][s * DM + kd];
        const u64 m2 = pack2(m, m);
        const ulonglong2* wo = (const ulonglong2*)(sWo + kd * DM);
        #pragma unroll
        for (int p = 0; p < 5; p++) {
            const ulonglong2 w = wo[p];
            ao2[2*p]   = fma2(m2, w.x, ao2[2*p]);
            ao2[2*p+1] = fma2(m2, w.y, ao2[2*p+1]);
        }
    }
    float r[DM];
    float mean = 0.f;
    #pragma unroll
    for (int p = 0; p < 10; p++) {
        float2 a = unpack2(ao2[p]);
        r[2*p]   = a.x + x[2*p];
        r[2*p+1] = a.y + x[2*p+1];
        mean += r[2*p] + r[2*p+1];
    }
    mean *= (1.0f / 20.0f);
    float var = 0.f;
    #pragma unroll
    for (int d = 0; d < DM; d++) { const float t = r[d] - mean; var = fmaf(t, t, var); }
    var *= (1.0f / 20.0f);
    const float rstd = rsqrtf(var + EPSV);

    float4* yo = (float4*)(g_y + row * DM);
    #pragma unroll
    for (int i = 0; i < 5; i++) {
        float4 t;
        t.x = (r[4*i+0] - mean) * rstd * sb[4][4*i+0] + sb[5][4*i+0];
        t.y = (r[4*i+1] - mean) * rstd * sb[4][4*i+1] + sb[5][4*i+1];
        t.z = (r[4*i+2] - mean) * rstd * sb[4][4*i+2] + sb[5][4*i+2];
        t.w = (r[4*i+3] - mean) * rstd * sb[4][4*i+3] + sb[5][4*i+3];
        yo[i] = t;
    }
}

// ======================================================================
// Kernel 2: FFN via mma.sync — PURE fp16 operands, fp32 accumulate.
// Single product everywhere (numerics ledger: 4 quantization sources
// x 4.6e-5 each in quadrature ≈ 1e-4 norm-rel, 10x margin to 1e-3).
// 512 threads (16 warps), 1 block/SM, 4 passes of 512 rows per block.
// ======================================================================
#define FW      16
#define FTHR    512
#define PASSES  4
#define GRID2   (NB * SQ / (FTHR / 32 * 32 * PASSES))  // 288

// smem byte offsets
#define O_W1    0                      // [512 n][36 k] f16 (rows 72B, pad)
#define O_W2    36864                  // [24 n][520 k] f16 (rows 1040B, pad)
#define O_STAGE 61824                  // [16 w][32 r][28 c] f32
#define SMEMF   (O_STAGE + FW * 32 * 28 * 4)   // 119168

__device__ __forceinline__ void mma16816(float* d,
                                         u32 a0, u32 a1, u32 a2, u32 a3,
                                         u32 b0, u32 b1) {
    asm volatile(
        "mma.sync.aligned.m16n8k16.row.col.f32.f16.f16.f32 "
        "{%0,%1,%2,%3}, {%4,%5,%6,%7}, {%8,%9}, {%0,%1,%2,%3};"
        : "+f"(d[0]), "+f"(d[1]), "+f"(d[2]), "+f"(d[3])
        : "r"(a0), "r"(a1), "r"(a2), "r"(a3), "r"(b0), "r"(b1));
}
__device__ __forceinline__ void mma1688(float* d, u32 a0, u32 a1, u32 b0) {
    asm volatile(
        "mma.sync.aligned.m16n8k8.row.col.f32.f16.f16.f32 "
        "{%0,%1,%2,%3}, {%4,%5}, {%6}, {%0,%1,%2,%3};"
        : "+f"(d[0]), "+f"(d[1]), "+f"(d[2]), "+f"(d[3])
        : "r"(a0), "r"(a1), "r"(b0));
}

__device__ __forceinline__ u32 cvt2(float x, float y) {
    __half2 hh = __floats2half2_rn(x, y);
    return *(u32*)&hh;
}
__device__ __forceinline__ u32 pack2relu(float x, float y) {
    __half2 hh = __floats2half2_rn(fmaxf(x, 0.f), fmaxf(y, 0.f));
    return *(u32*)&hh;
}

__global__ void __launch_bounds__(FTHR, 1) k_ffn3(
    const float* __restrict__ W1, const float* __restrict__ W2,
    const float* __restrict__ g2, const float* __restrict__ b2,
    float* __restrict__ Out)
{
    extern __shared__ __align__(16) char sm[];
    const int tid = threadIdx.x;

    // ---- stage W1^T fp16: [n=512][k=36 pad], rows 72B ----
    for (int i = tid; i < DFF * 36; i += FTHR) {
        const int n = i / 36, k = i - n * 36;
        const float v = (k < DM) ? W1[k * DFF + n] : 0.f;
        *(__half*)(sm + O_W1 + n * 72 + k * 2) = __float2half_rn(v);
    }
    // ---- stage W2^T fp16: [n=24 pad][k=520 pad], rows 1040B ----
    for (int i = tid; i < 24 * 520; i += FTHR) {
        const int n = i / 520, k = i - n * 520;
        const float v = (n < DM && k < DFF) ? W2[k * DM + n] : 0.f;
        *(__half*)(sm + O_W2 + n * 1040 + k * 2) = __float2half_rn(v);
    }
    __syncthreads();

    const int w    = tid >> 5;
    const int lane = tid & 31;
    const int r    = lane >> 2;
    const int c    = lane & 3;
    float* stg = (float*)(sm + O_STAGE) + w * (32 * 28);

    #pragma unroll 1
    for (int pass = 0; pass < PASSES; pass++) {
        const size_t wbase = ((size_t)blockIdx.x * PASSES + pass) * (size_t)(FW * 32)
                           + (size_t)w * 32;

        // ---- y A-fragments (fp16), K padded 20 -> 32 ----
        // [0..3] = ktile0 (k16); [4],[5] = k-tail (k8, valid c<2)
        u32 ah[2][6];
        #pragma unroll
        for (int m = 0; m < 2; m++) {
            const float* y0 = g_y + (wbase + m * 16 + r) * DM;
            const float* y1 = y0 + 8 * DM;
            float2 p;
            p = *(const float2*)(y0 + 2 * c);     ah[m][0] = cvt2(p.x, p.y);
            p = *(const float2*)(y1 + 2 * c);     ah[m][1] = cvt2(p.x, p.y);
            p = *(const float2*)(y0 + 2 * c + 8); ah[m][2] = cvt2(p.x, p.y);
            p = *(const float2*)(y1 + 2 * c + 8); ah[m][3] = cvt2(p.x, p.y);
            if (c < 2) {
                p = *(const float2*)(y0 + 16 + 2 * c); ah[m][4] = cvt2(p.x, p.y);
                p = *(const float2*)(y1 + 16 + 2 * c); ah[m][5] = cvt2(p.x, p.y);
            } else {
                ah[m][4] = ah[m][5] = 0u;
            }
        }

        float d2[3][2][4];
        #pragma unroll
        for (int n = 0; n < 3; n++)
            #pragma unroll
            for (int m = 0; m < 2; m++)
                #pragma unroll
                for (int i = 0; i < 4; i++) d2[n][m][i] = 0.f;

        #pragma unroll 1
        for (int ch = 0; ch < 16; ch++) {
            // ---- GEMM1: D1[32 rows x 32 n], K = 16 (k16) + 8 (k8 tail) ----
            float d1[4][2][4];
            #pragma unroll
            for (int n = 0; n < 4; n++)
                #pragma unroll
                for (int m = 0; m < 2; m++)
                    #pragma unroll
                    for (int i = 0; i < 4; i++) d1[n][m][i] = 0.f;

            #pragma unroll
            for (int nt = 0; nt < 4; nt++) {
                const u32 boff = (u32)((ch * 32 + nt * 8 + r) * 72 + c * 4);
                const u32 bh0 = *(const u32*)(sm + O_W1 + boff);
                const u32 bh1 = *(const u32*)(sm + O_W1 + boff + 16);
                const u32 th0 = *(const u32*)(sm + O_W1 + boff + 32);
                #pragma unroll
                for (int m = 0; m < 2; m++) {
                    mma16816(d1[nt][m], ah[m][0], ah[m][1], ah[m][2], ah[m][3], bh0, bh1);
                    mma1688(d1[nt][m], ah[m][4], ah[m][5], th0);
                }
            }

            // ---- per k-subtile: relu-pack D1 -> A2 frags, GEMM2 (1 product) ----
            #pragma unroll
            for (int kt2 = 0; kt2 < 2; kt2++) {
                u32 fh[2][4];
                #pragma unroll
                for (int m = 0; m < 2; m++) {
                    const float* dA = d1[2 * kt2][m];      // -> a0, a1
                    const float* dB = d1[2 * kt2 + 1][m];  // -> a2, a3
                    fh[m][0] = pack2relu(dA[0], dA[1]);
                    fh[m][1] = pack2relu(dA[2], dA[3]);
                    fh[m][2] = pack2relu(dB[0], dB[1]);
                    fh[m][3] = pack2relu(dB[2], dB[3]);
                }
                #pragma unroll
                for (int nt2 = 0; nt2 < 3; nt2++) {
                    const u32 boff = (u32)((nt2 * 8 + r) * 1040
                                   + (ch * 32 + kt2 * 16) * 2 + c * 4);
                    const u32 bh0 = *(const u32*)(sm + O_W2 + boff);
                    const u32 bh1 = *(const u32*)(sm + O_W2 + boff + 16);
                    #pragma unroll
                    for (int m = 0; m < 2; m++)
                        mma16816(d2[nt2][m], fh[m][0], fh[m][1], fh[m][2], fh[m][3], bh0, bh1);
                }
            }
        }

        // ---- epilogue: D2 frags -> staging -> per-lane residual + LN2 ----
        #pragma unroll
        for (int nt2 = 0; nt2 < 3; nt2++) {
            #pragma unroll
            for (int m = 0; m < 2; m++) {
                float* s0 = stg + (m * 16 + r) * 28 + nt2 * 8 + 2 * c;
                s0[0]  = d2[nt2][m][0];
                s0[1]  = d2[nt2][m][1];
                float* s1 = s0 + 8 * 28;
                s1[0]  = d2[nt2][m][2];
                s1[1]  = d2[nt2][m][3];
            }
        }
        __syncwarp();

        {
            const size_t gr = wbase + lane;
            const float* yr = g_y + gr * DM;
            const float* fr = stg + lane * 28;
            float rr[DM];
            float mean = 0.f;
            #pragma unroll
            for (int d = 0; d < DM; d++) {
                rr[d] = yr[d] + fr[d];
                mean += rr[d];
            }
            mean *= (1.0f / 20.0f);
            float var = 0.f;
            #pragma unroll
            for (int d = 0; d < DM; d++) { const float t = rr[d] - mean; var = fmaf(t, t, var); }
            var *= (1.0f / 20.0f);
            const float rstd = rsqrtf(var + EPSV);
            float4* o4 = (float4*)(Out + gr * DM);
            #pragma unroll
            for (int i = 0; i < 5; i++) {
                float4 o;
                o.x = (rr[4*i+0] - mean) * rstd * g2[4*i+0] + b2[4*i+0];
                o.y = (rr[4*i+1] - mean) * rstd * g2[4*i+1] + b2[4*i+1];
                o.z = (rr[4*i+2] - mean) * rstd * g2[4*i+2] + b2[4*i+2];
                o.w = (rr[4*i+3] - mean) * rstd * g2[4*i+3] + b2[4*i+3];
                o4[i] = o;
            }
        }
        __syncwarp();
    }
}

// ======================================================================
// Launch
// ======================================================================
extern "C" void kernel_launch(void* const* d_in, const int* in_sizes, int n_in,
                              void* d_out, int out_size)
{
    (void)in_sizes; (void)n_in; (void)out_size;
    const float* X  = (const float*)d_in[0];
    const float* Wq = (const float*)d_in[1];
    const float* bq = (const float*)d_in[2];
    const float* Wk = (const float*)d_in[3];
    const float* bk = (const float*)d_in[4];
    const float* Wv = (const float*)d_in[5];
    const float* bv = (const float*)d_in[6];
    const float* Wo = (const float*)d_in[7];
    const float* bo = (const float*)d_in[8];
    const float* g1 = (const float*)d_in[9];
    const float* b1 = (const float*)d_in[10];
    const float* W1 = (const float*)d_in[11];
    const float* W2 = (const float*)d_in[12];
    const float* g2 = (const float*)d_in[13];
    const float* b2 = (const float*)d_in[14];
    float* Out = (float*)d_out;

    cudaFuncSetAttribute(k_ffn3, cudaFuncAttributeMaxDynamicSharedMemorySize, SMEMF);

    k_attn<<<NB / GB, T1>>>(X, Wq, bq, Wk, bk, Wv, bv, Wo, bo, g1, b1);
    k_ffn3<<<GRID2, FTHR, SMEMF>>>(W1, W2, g2, b2, Out);
}

// round 14
// speedup vs baseline: 3.4315x; 1.1440x over previous
#include <cuda_runtime.h>
#include <cuda_fp16.h>
#include <cstdint>

#define NB   65536
#define SQ   9
#define DM   20
#define NH   4
#define DHD  5
#define DFF  512
#define EPSV 1e-5f

typedef unsigned long long u64;
typedef unsigned int u32;

// scratch: y = LN1(attn_out + x), fp32 (exact, needed for residual)
__device__ __align__(16) float g_y[(size_t)NB * SQ * DM];

// ---------------- mma helpers ----------------
__device__ __forceinline__ void mma16816(float* d,
                                         u32 a0, u32 a1, u32 a2, u32 a3,
                                         u32 b0, u32 b1) {
    asm volatile(
        "mma.sync.aligned.m16n8k16.row.col.f32.f16.f16.f32 "
        "{%0,%1,%2,%3}, {%4,%5,%6,%7}, {%8,%9}, {%0,%1,%2,%3};"
        : "+f"(d[0]), "+f"(d[1]), "+f"(d[2]), "+f"(d[3])
        : "r"(a0), "r"(a1), "r"(a2), "r"(a3), "r"(b0), "r"(b1));
}
__device__ __forceinline__ void mma1688(float* d, u32 a0, u32 a1, u32 b0) {
    asm volatile(
        "mma.sync.aligned.m16n8k8.row.col.f32.f16.f16.f32 "
        "{%0,%1,%2,%3}, {%4,%5}, {%6}, {%0,%1,%2,%3};"
        : "+f"(d[0]), "+f"(d[1]), "+f"(d[2]), "+f"(d[3])
        : "r"(a0), "r"(a1), "r"(b0));
}
__device__ __forceinline__ u32 cvt2(float x, float y) {
    __half2 hh = __floats2half2_rn(x, y);
    return *(u32*)&hh;
}
__device__ __forceinline__ u32 pack2relu(float x, float y) {
    __half2 hh = __floats2half2_rn(x, y);
    hh = __hmax2(hh, __float2half2_rn(0.f));
    return *(u32*)&hh;
}

// ======================================================================
// Kernel 1: attention + LN1, QKV/Wo via mma.sync (fp16), softmax fp32.
// 288 threads = 9 warps = 32 batches (288 rows). thread = row.
// ======================================================================
#define AT 288
#define GRID1 (NB / 32)   // 2048

// smem byte offsets
#define A_WQKV 0                       // [64 n][24 k] half = 3072
#define A_WO   3072                    // [24 n][24 k] half = 1152
#define A_BQKV 4224                    // 64 f
#define A_BO   4480                    // 24 f
#define A_G1   4576                    // 20 f
#define A_B1   4656                    // 20 f (ends 4736)
#define A_M    4736                    // [288][24] f = 27648 (ends 32384)
#define A_U    32384                   // union: sQKV [288][69] f = 79488
                                       //        stage [9][32][29] f = 33408
#define SMEM1  (A_U + 288 * 69 * 4)    // 111872

__global__ void __launch_bounds__(AT, 2) k_attn3(
    const float* __restrict__ X,
    const float* __restrict__ Wq, const float* __restrict__ bq,
    const float* __restrict__ Wk, const float* __restrict__ bk,
    const float* __restrict__ Wv, const float* __restrict__ bv,
    const float* __restrict__ Wo, const float* __restrict__ bo,
    const float* __restrict__ g1, const float* __restrict__ b1)
{
    extern __shared__ __align__(16) char sm1[];
    __half* sWqkv = (__half*)(sm1 + A_WQKV);
    __half* sWo   = (__half*)(sm1 + A_WO);
    float*  sBqkv = (float*)(sm1 + A_BQKV);
    float*  sBo   = (float*)(sm1 + A_BO);
    float*  sG1   = (float*)(sm1 + A_G1);
    float*  sB1   = (float*)(sm1 + A_B1);
    float*  sM    = (float*)(sm1 + A_M);    // [288][24]
    float*  sQKV  = (float*)(sm1 + A_U);    // [288][69]
    float*  stage = (float*)(sm1 + A_U);    // alias [9][32][29]

    const int tid  = threadIdx.x;
    const int w    = tid >> 5;
    const int lane = tid & 31;
    const int r    = lane >> 2;
    const int c    = lane & 3;

    // ---- stage weights (fp16) + biases ----
    for (int i = tid; i < 64 * 24; i += AT) {
        const int n = i / 24, k = i - n * 24;
        float v = 0.f;
        if (k < DM) {
            if (n < 20)      v = Wq[k * DM + n];
            else if (n < 40) v = Wk[k * DM + n - 20];
            else if (n < 60) v = Wv[k * DM + n - 40];
        }
        sWqkv[n * 24 + k] = __float2half_rn(v);
    }
    for (int i = tid; i < 24 * 24; i += AT) {
        const int n = i / 24, k = i - n * 24;
        sWo[n * 24 + k] = __float2half_rn((n < DM && k < DM) ? Wo[k * DM + n] : 0.f);
    }
    if (tid < 64)
        sBqkv[tid] = (tid < 20) ? bq[tid]
                   : (tid < 40) ? bk[tid - 20]
                   : (tid < 60) ? bv[tid - 40] : 0.f;
    if (tid < 24) sBo[tid] = (tid < DM) ? bo[tid] : 0.f;
    if (tid < DM) { sG1[tid] = g1[tid]; sB1[tid] = b1[tid]; }

    const size_t rowbase = (size_t)blockIdx.x * AT;
    const size_t myrow   = rowbase + tid;

    // x row in regs (residual)
    float x[DM];
    {
        const float4* xr = (const float4*)(X + myrow * DM);
        #pragma unroll
        for (int i = 0; i < 5; i++) {
            float4 t = xr[i];
            x[4*i] = t.x; x[4*i+1] = t.y; x[4*i+2] = t.z; x[4*i+3] = t.w;
        }
    }
    __syncthreads();

    // ---- QKV GEMM: [32 rows x 20] @ [20 x 64] per warp ----
    {
        u32 a[2][6];
        #pragma unroll
        for (int m = 0; m < 2; m++) {
            const float* x0 = X + (rowbase + w * 32 + m * 16 + r) * DM;
            const float* x1 = x0 + 8 * DM;
            float2 p;
            p = *(const float2*)(x0 + 2 * c);     a[m][0] = cvt2(p.x, p.y);
            p = *(const float2*)(x1 + 2 * c);     a[m][1] = cvt2(p.x, p.y);
            p = *(const float2*)(x0 + 2 * c + 8); a[m][2] = cvt2(p.x, p.y);
            p = *(const float2*)(x1 + 2 * c + 8); a[m][3] = cvt2(p.x, p.y);
            if (c < 2) {
                p = *(const float2*)(x0 + 16 + 2 * c); a[m][4] = cvt2(p.x, p.y);
                p = *(const float2*)(x1 + 16 + 2 * c); a[m][5] = cvt2(p.x, p.y);
            } else {
                a[m][4] = a[m][5] = 0u;
            }
        }
        #pragma unroll
        for (int nt = 0; nt < 8; nt++) {
            const char* bb = (const char*)sWqkv + (nt * 8 + r) * 48 + c * 4;
            const u32 b0 = *(const u32*)bb;
            const u32 b1 = *(const u32*)(bb + 16);
            const u32 t0 = *(const u32*)(bb + 32);
            #pragma unroll
            for (int m = 0; m < 2; m++) {
                float d[4] = {0.f, 0.f, 0.f, 0.f};
                mma16816(d, a[m][0], a[m][1], a[m][2], a[m][3], b0, b1);
                mma1688(d, a[m][4], a[m][5], t0);
                const int C  = nt * 8 + 2 * c;
                const int R0 = w * 32 + m * 16 + r;
                sQKV[R0 * 69 + C]       = d[0] + sBqkv[C];
                sQKV[R0 * 69 + C + 1]   = d[1] + sBqkv[C + 1];
                sQKV[(R0+8) * 69 + C]     = d[2] + sBqkv[C];
                sQKV[(R0+8) * 69 + C + 1] = d[3] + sBqkv[C + 1];
            }
        }
    }
    __syncthreads();

    // ---- attention (fp32 scalar, champion core) ----
    {
        const int bl = tid / SQ;
        const int s  = tid - bl * SQ;
        float q[DM];
        #pragma unroll
        for (int d = 0; d < DM; d++) q[d] = sQKV[tid * 69 + d];

        #pragma unroll
        for (int h = 0; h < NH; h++) {
            float sc[SQ];
            float mx = -1e30f;
            #pragma unroll
            for (int j = 0; j < SQ; j++) {
                const float* kr = sQKV + (bl * SQ + j) * 69 + 20 + h * DHD;
                float a = 0.f;
                #pragma unroll
                for (int dh = 0; dh < DHD; dh++)
                    a = fmaf(q[h * DHD + dh], kr[dh], a);
                a *= (1.0f / 3.0f);
                sc[j] = a;
                mx = fmaxf(mx, a);
            }
            float den = 0.f;
            #pragma unroll
            for (int j = 0; j < SQ; j++) { sc[j] = __expf(sc[j] - mx); den += sc[j]; }
            const float inv = 1.0f / den;
            float ctx[DHD] = {0.f, 0.f, 0.f, 0.f, 0.f};
            #pragma unroll
            for (int j = 0; j < SQ; j++) {
                const float p = sc[j];
                const float* vr = sQKV + (bl * SQ + j) * 69 + 40 + h * DHD;
                #pragma unroll
                for (int dh = 0; dh < DHD; dh++)
                    ctx[dh] = fmaf(p, vr[dh], ctx[dh]);
            }
            // quirk merge: f = h*45 + dh*9 + s -> merged[f/20][f%20]
            #pragma unroll
            for (int dh = 0; dh < DHD; dh++) {
                const int f = h * 45 + dh * 9 + s;
                sM[(bl * SQ + f / 20) * 24 + (f % 20)] = ctx[dh] * inv;
            }
        }
        // zero pad cols [20,24) of own row
        sM[tid * 24 + 20] = 0.f; sM[tid * 24 + 21] = 0.f;
        sM[tid * 24 + 22] = 0.f; sM[tid * 24 + 23] = 0.f;
    }
    __syncthreads();

    // ---- Wo GEMM: [32 rows x 20] @ [20 x 20(24)] per warp ----
    {
        u32 a[2][6];
        #pragma unroll
        for (int m = 0; m < 2; m++) {
            const float* m0 = sM + (w * 32 + m * 16 + r) * 24;
            const float* m1 = m0 + 8 * 24;
            float2 p;
            p = *(const float2*)(m0 + 2 * c);      a[m][0] = cvt2(p.x, p.y);
            p = *(const float2*)(m1 + 2 * c);      a[m][1] = cvt2(p.x, p.y);
            p = *(const float2*)(m0 + 2 * c + 8);  a[m][2] = cvt2(p.x, p.y);
            p = *(const float2*)(m1 + 2 * c + 8);  a[m][3] = cvt2(p.x, p.y);
            // pad cols 20..23 are zeroed, so unconditional tail load is safe
            p = *(const float2*)(m0 + 16 + 2 * c); a[m][4] = cvt2(p.x, p.y);
            p = *(const float2*)(m1 + 16 + 2 * c); a[m][5] = cvt2(p.x, p.y);
        }
        float* st = stage + w * (32 * 29);
        #pragma unroll
        for (int nt = 0; nt < 3; nt++) {
            const char* bb = (const char*)sWo + (nt * 8 + r) * 48 + c * 4;
            const u32 b0 = *(const u32*)bb;
            const u32 b1 = *(const u32*)(bb + 16);
            const u32 t0 = *(const u32*)(bb + 32);
            #pragma unroll
            for (int m = 0; m < 2; m++) {
                float d[4] = {0.f, 0.f, 0.f, 0.f};
                mma16816(d, a[m][0], a[m][1], a[m][2], a[m][3], b0, b1);
                mma1688(d, a[m][4], a[m][5], t0);
                const int C  = nt * 8 + 2 * c;
                const int R0 = m * 16 + r;
                st[R0 * 29 + C]       = d[0];
                st[R0 * 29 + C + 1]   = d[1];
                st[(R0+8) * 29 + C]     = d[2];
                st[(R0+8) * 29 + C + 1] = d[3];
            }
        }
    }
    __syncwarp();

    // ---- epilogue: attn_out + bo + x -> LN1 -> g_y ----
    {
        const float* ao = stage + w * (32 * 29) + lane * 29;
        float rr[DM];
        float mean = 0.f;
        #pragma unroll
        for (int d = 0; d < DM; d++) {
            rr[d] = ao[d] + sBo[d] + x[d];
            mean += rr[d];
        }
        mean *= (1.0f / 20.0f);
        float var = 0.f;
        #pragma unroll
        for (int d = 0; d < DM; d++) { const float t = rr[d] - mean; var = fmaf(t, t, var); }
        var *= (1.0f / 20.0f);
        const float rstd = rsqrtf(var + EPSV);

        float4* yo = (float4*)(g_y + myrow * DM);
        #pragma unroll
        for (int i = 0; i < 5; i++) {
            float4 t;
            t.x = (rr[4*i+0] - mean) * rstd * sG1[4*i+0] + sB1[4*i+0];
            t.y = (rr[4*i+1] - mean) * rstd * sG1[4*i+1] + sB1[4*i+1];
            t.z = (rr[4*i+2] - mean) * rstd * sG1[4*i+2] + sB1[4*i+2];
            t.w = (rr[4*i+3] - mean) * rstd * sG1[4*i+3] + sB1[4*i+3];
            yo[i] = t;
        }
    }
}

// ======================================================================
// Kernel 2: FFN via mma.sync — pure fp16 operands, fp32 accumulate.
// (R13 champion; relu moved to fp16 domain via hmax2)
// ======================================================================
#define FW      16
#define FTHR    512
#define PASSES  4
#define GRID2   (NB * SQ / (FTHR / 32 * 32 * PASSES))  // 288

#define O_W1    0
#define O_W2    36864
#define O_STAGE 61824
#define SMEMF   (O_STAGE + FW * 32 * 28 * 4)   // 119168

__global__ void __launch_bounds__(FTHR, 1) k_ffn3(
    const float* __restrict__ W1, const float* __restrict__ W2,
    const float* __restrict__ g2, const float* __restrict__ b2,
    float* __restrict__ Out)
{
    extern __shared__ __align__(16) char sm[];
    const int tid = threadIdx.x;

    for (int i = tid; i < DFF * 36; i += FTHR) {
        const int n = i / 36, k = i - n * 36;
        const float v = (k < DM) ? W1[k * DFF + n] : 0.f;
        *(__half*)(sm + O_W1 + n * 72 + k * 2) = __float2half_rn(v);
    }
    for (int i = tid; i < 24 * 520; i += FTHR) {
        const int n = i / 520, k = i - n * 520;
        const float v = (n < DM && k < DFF) ? W2[k * DM + n] : 0.f;
        *(__half*)(sm + O_W2 + n * 1040 + k * 2) = __float2half_rn(v);
    }
    __syncthreads();

    const int w    = tid >> 5;
    const int lane = tid & 31;
    const int r    = lane >> 2;
    const int c    = lane & 3;
    float* stg = (float*)(sm + O_STAGE) + w * (32 * 28);

    #pragma unroll 1
    for (int pass = 0; pass < PASSES; pass++) {
        const size_t wbase = ((size_t)blockIdx.x * PASSES + pass) * (size_t)(FW * 32)
                           + (size_t)w * 32;

        u32 ah[2][6];
        #pragma unroll
        for (int m = 0; m < 2; m++) {
            const float* y0 = g_y + (wbase + m * 16 + r) * DM;
            const float* y1 = y0 + 8 * DM;
            float2 p;
            p = *(const float2*)(y0 + 2 * c);     ah[m][0] = cvt2(p.x, p.y);
            p = *(const float2*)(y1 + 2 * c);     ah[m][1] = cvt2(p.x, p.y);
            p = *(const float2*)(y0 + 2 * c + 8); ah[m][2] = cvt2(p.x, p.y);
            p = *(const float2*)(y1 + 2 * c + 8); ah[m][3] = cvt2(p.x, p.y);
            if (c < 2) {
                p = *(const float2*)(y0 + 16 + 2 * c); ah[m][4] = cvt2(p.x, p.y);
                p = *(const float2*)(y1 + 16 + 2 * c); ah[m][5] = cvt2(p.x, p.y);
            } else {
                ah[m][4] = ah[m][5] = 0u;
            }
        }

        float d2[3][2][4];
        #pragma unroll
        for (int n = 0; n < 3; n++)
            #pragma unroll
            for (int m = 0; m < 2; m++)
                #pragma unroll
                for (int i = 0; i < 4; i++) d2[n][m][i] = 0.f;

        #pragma unroll 1
        for (int ch = 0; ch < 16; ch++) {
            float d1[4][2][4];
            #pragma unroll
            for (int n = 0; n < 4; n++)
                #pragma unroll
                for (int m = 0; m < 2; m++)
                    #pragma unroll
                    for (int i = 0; i < 4; i++) d1[n][m][i] = 0.f;

            #pragma unroll
            for (int nt = 0; nt < 4; nt++) {
                const u32 boff = (u32)((ch * 32 + nt * 8 + r) * 72 + c * 4);
                const u32 bh0 = *(const u32*)(sm + O_W1 + boff);
                const u32 bh1 = *(const u32*)(sm + O_W1 + boff + 16);
                const u32 th0 = *(const u32*)(sm + O_W1 + boff + 32);
                #pragma unroll
                for (int m = 0; m < 2; m++) {
                    mma16816(d1[nt][m], ah[m][0], ah[m][1], ah[m][2], ah[m][3], bh0, bh1);
                    mma1688(d1[nt][m], ah[m][4], ah[m][5], th0);
                }
            }

            #pragma unroll
            for (int kt2 = 0; kt2 < 2; kt2++) {
                u32 fh[2][4];
                #pragma unroll
                for (int m = 0; m < 2; m++) {
                    const float* dA = d1[2 * kt2][m];
                    const float* dB = d1[2 * kt2 + 1][m];
                    fh[m][0] = pack2relu(dA[0], dA[1]);
                    fh[m][1] = pack2relu(dA[2], dA[3]);
                    fh[m][2] = pack2relu(dB[0], dB[1]);
                    fh[m][3] = pack2relu(dB[2], dB[3]);
                }
                #pragma unroll
                for (int nt2 = 0; nt2 < 3; nt2++) {
                    const u32 boff = (u32)((nt2 * 8 + r) * 1040
                                   + (ch * 32 + kt2 * 16) * 2 + c * 4);
                    const u32 bh0 = *(const u32*)(sm + O_W2 + boff);
                    const u32 bh1 = *(const u32*)(sm + O_W2 + boff + 16);
                    #pragma unroll
                    for (int m = 0; m < 2; m++)
                        mma16816(d2[nt2][m], fh[m][0], fh[m][1], fh[m][2], fh[m][3], bh0, bh1);
                }
            }
        }

        #pragma unroll
        for (int nt2 = 0; nt2 < 3; nt2++) {
            #pragma unroll
            for (int m = 0; m < 2; m++) {
                float* s0 = stg + (m * 16 + r) * 28 + nt2 * 8 + 2 * c;
                s0[0]  = d2[nt2][m][0];
                s0[1]  = d2[nt2][m][1];
                float* s1 = s0 + 8 * 28;
                s1[0]  = d2[nt2][m][2];
                s1[1]  = d2[nt2][m][3];
            }
        }
        __syncwarp();

        {
            const size_t gr = wbase + lane;
            const float* yr = g_y + gr * DM;
            const float* fr = stg + lane * 28;
            float rr[DM];
            float mean = 0.f;
            #pragma unroll
            for (int d = 0; d < DM; d++) {
                rr[d] = yr[d] + fr[d];
                mean += rr[d];
            }
            mean *= (1.0f / 20.0f);
            float var = 0.f;
            #pragma unroll
            for (int d = 0; d < DM; d++) { const float t = rr[d] - mean; var = fmaf(t, t, var); }
            var *= (1.0f / 20.0f);
            const float rstd = rsqrtf(var + EPSV);
            float4* o4 = (float4*)(Out + gr * DM);
            #pragma unroll
            for (int i = 0; i < 5; i++) {
                float4 o;
                o.x = (rr[4*i+0] - mean) * rstd * g2[4*i+0] + b2[4*i+0];
                o.y = (rr[4*i+1] - mean) * rstd * g2[4*i+1] + b2[4*i+1];
                o.z = (rr[4*i+2] - mean) * rstd * g2[4*i+2] + b2[4*i+2];
                o.w = (rr[4*i+3] - mean) * rstd * g2[4*i+3] + b2[4*i+3];
                o4[i] = o;
            }
        }
        __syncwarp();
    }
}

// ======================================================================
// Launch
// ======================================================================
extern "C" void kernel_launch(void* const* d_in, const int* in_sizes, int n_in,
                              void* d_out, int out_size)
{
    (void)in_sizes; (void)n_in; (void)out_size;
    const float* X  = (const float*)d_in[0];
    const float* Wq = (const float*)d_in[1];
    const float* bq = (const float*)d_in[2];
    const float* Wk = (const float*)d_in[3];
    const float* bk = (const float*)d_in[4];
    const float* Wv = (const float*)d_in[5];
    const float* bv = (const float*)d_in[6];
    const float* Wo = (const float*)d_in[7];
    const float* bo = (const float*)d_in[8];
    const float* g1 = (const float*)d_in[9];
    const float* b1 = (const float*)d_in[10];
    const float* W1 = (const float*)d_in[11];
    const float* W2 = (const float*)d_in[12];
    const float* g2 = (const float*)d_in[13];
    const float* b2 = (const float*)d_in[14];
    float* Out = (float*)d_out;

    cudaFuncSetAttribute(k_attn3, cudaFuncAttributeMaxDynamicSharedMemorySize, SMEM1);
    cudaFuncSetAttribute(k_ffn3, cudaFuncAttributeMaxDynamicSharedMemorySize, SMEMF);

    k_attn3<<<GRID1, AT, SMEM1>>>(X, Wq, bq, Wk, bk, Wv, bv, Wo, bo, g1, b1);
    k_ffn3<<<GRID2, FTHR, SMEMF>>>(W1, W2, g2, b2, Out);
}